// round 11
// baseline (speedup 1.0000x reference)
#include <cuda_runtime.h>
#include <cuda_fp16.h>
#include <math.h>

#define DM     1024
#define NH     16
#define DH     64
#define BATCH  4
#define SEQ    2048
#define TOKENS (BATCH * SEQ)

// ---------------------------------------------------------------------------
// Scratch (static device memory). Fully single-term fp16 scheme.
// ---------------------------------------------------------------------------
__device__ __align__(16) __half g_xhi[TOKENS * DM];
__device__ __align__(16) __half g_wqkv_hi[3 * DM * DM];
__device__ __align__(16) __half g_wo_hi[DM * DM];
__device__ __align__(16) __half g_ahi[TOKENS * DM];
__device__ __align__(16) __half g_Qhi[TOKENS * DM];   // pre-scaled by 0.125
__device__ __align__(16) __half g_Khi[TOKENS * DM];
__device__ __align__(16) __half g_Vhi[TOKENS * DM];

// ---------------------------------------------------------------------------
// helpers
// ---------------------------------------------------------------------------
__device__ __forceinline__ unsigned smem_to_u32(const void* p) {
    unsigned a;
    asm("{ .reg .u64 t; cvta.to.shared.u64 t, %1; cvt.u32.u64 %0, t; }"
        : "=r"(a) : "l"(p));
    return a;
}

#define CP_ASYNC16(saddr, gptr) \
    asm volatile("cp.async.cg.shared.global [%0], [%1], 16;" \
                 :: "r"((unsigned)(saddr)), "l"(gptr))
#define CP_COMMIT() asm volatile("cp.async.commit_group;" ::: "memory")
#define CP_WAIT(n)  asm volatile("cp.async.wait_group %0;" :: "n"(n) : "memory")

__device__ __forceinline__ void ldsm_x4(unsigned& r0, unsigned& r1,
                                        unsigned& r2, unsigned& r3,
                                        unsigned addr) {
    asm volatile("ldmatrix.sync.aligned.m8n8.x4.shared.b16 {%0,%1,%2,%3}, [%4];"
                 : "=r"(r0), "=r"(r1), "=r"(r2), "=r"(r3) : "r"(addr));
}

__device__ __forceinline__ void ldsm_x4_t(unsigned& r0, unsigned& r1,
                                          unsigned& r2, unsigned& r3,
                                          unsigned addr) {
    asm volatile("ldmatrix.sync.aligned.m8n8.x4.trans.shared.b16 {%0,%1,%2,%3}, [%4];"
                 : "=r"(r0), "=r"(r1), "=r"(r2), "=r"(r3) : "r"(addr));
}

__device__ __forceinline__ void mma16816(float* d, const unsigned* a,
                                         const unsigned* b) {
    asm volatile(
        "mma.sync.aligned.m16n8k16.row.col.f32.f16.f16.f32 "
        "{%0,%1,%2,%3}, {%4,%5,%6,%7}, {%8,%9}, {%0,%1,%2,%3};"
        : "+f"(d[0]), "+f"(d[1]), "+f"(d[2]), "+f"(d[3])
        : "r"(a[0]), "r"(a[1]), "r"(a[2]), "r"(a[3]), "r"(b[0]), "r"(b[1]));
}

__device__ __forceinline__ unsigned pack_h2(__half a, __half b) {
    __half2 t = __halves2half2(a, b);
    return *(unsigned*)&t;
}

// ---------------------------------------------------------------------------
// fp32 -> fp16 convert. mode 0: x ; mode 1: Wqkv ; mode 2: Wo
// ---------------------------------------------------------------------------
__global__ void __launch_bounds__(256) split_kernel(
    const float* __restrict__ src, int mode, int n4)
{
    int i = blockIdx.x * blockDim.x + threadIdx.x;
    if (i >= n4) return;
    float4 v = ((const float4*)src)[i];
    __half* hp = (mode == 0) ? g_xhi : (mode == 1) ? g_wqkv_hi : g_wo_hi;
    ((unsigned*)hp)[2 * i] =
        pack_h2(__float2half_rn(v.x), __float2half_rn(v.y));
    ((unsigned*)hp)[2 * i + 1] =
        pack_h2(__float2half_rn(v.z), __float2half_rn(v.w));
}

// ---------------------------------------------------------------------------
// Tensor-core GEMM, single-term fp16: C = A·B^T + bias. K=1024.
// CTA 128(M)x256(N), 8 warps 2x4, warp tile 64x64 (128 B/MMA of LDSM),
// BK=32, 3-stage cp.async, one __syncthreads per chunk, 1 CTA/SM.
// MODE 0: A=xhi, B=Wqkv -> Q(fp16, scaled 0.125), K, V in [B,H,S,DH]
// MODE 1: A=ahi, B=Wo  -> fp32 row-major Cout
// ---------------------------------------------------------------------------
#define GTILE_A 10240                // 128 rows x 80B pitch
#define GTILE_B 20480                // 256 rows x 80B pitch
#define GSTAGE  (GTILE_A + GTILE_B)  // 30720
#define GEMM_SMEM (3 * GSTAGE)       // 92160 (3 stages)

template <int MODE>
__global__ void __launch_bounds__(256, 1) tc_gemm_kernel(
    const float* __restrict__ bias, float* __restrict__ Cout)
{
    extern __shared__ __align__(16) char gsm[];

    const int tid  = threadIdx.x;
    const int lane = tid & 31;
    const int wid  = tid >> 5;
    const int n0 = blockIdx.x << 8;      // 256-wide N tile
    const int m0 = blockIdx.y << 7;      // 128-wide M tile
    const int warp_m = (wid & 1) << 6;   // 0,64
    const int warp_n = (wid >> 1) << 6;  // 0,64,128,192
    const unsigned sbase = smem_to_u32(gsm);

    const __half* Ahi = (MODE == 0) ? g_xhi : g_ahi;
    const __half* Bhi = (MODE == 0) ? g_wqkv_hi : g_wo_hi;

    // staging: A rows tid>>2 (+64); B rows tid>>2 (+64,+128,+192); quad tid&3
    const int rowS = tid >> 2;
    const int quad = tid & 3;
    const __half* pA = Ahi + (size_t)(m0 + rowS) * DM + quad * 8;
    const __half* pB = Bhi + (size_t)(n0 + rowS) * DM + quad * 8;
    const unsigned soA = rowS * 80 + quad * 16;
    const unsigned soB = GTILE_A + rowS * 80 + quad * 16;

    // fragment lane addressing
    const unsigned aHi0 = sbase + (warp_m + (lane & 15)) * 80 + ((lane >> 4) << 4);
    const unsigned bRow = warp_n + ((lane >> 4) << 3) + (lane & 7);
    const unsigned bHi0 = sbase + GTILE_A + bRow * 80 + (((lane >> 3) & 1) << 4);

    float acc[4][8][4] = {};

    // prologue: chunks 0,1 -> stages 0,1
#pragma unroll
    for (int p = 0; p < 2; p++) {
        const unsigned st = sbase + p * GSTAGE;
        const int kc = p * 32;
        CP_ASYNC16(st + soA, pA + kc);
        CP_ASYNC16(st + soA + 64 * 80, pA + (size_t)64 * DM + kc);
#pragma unroll
        for (int r = 0; r < 4; r++)
            CP_ASYNC16(st + soB + r * (64 * 80), pB + (size_t)(64 * r) * DM + kc);
        CP_COMMIT();
    }

    int stage = 0;
    for (int c = 0; c < 32; c++) {
        if (c <= 29) { CP_WAIT(1); } else { CP_WAIT(0); }
        __syncthreads();

        const unsigned stof = (unsigned)stage * GSTAGE;
        const unsigned aHi = aHi0 + stof;
        const unsigned bHi = bHi0 + stof;

#pragma unroll
        for (int ks2 = 0; ks2 < 2; ks2++) {
            const unsigned kb = ks2 << 5;
            unsigned af[4][4], bf[8][2];
#pragma unroll
            for (int i = 0; i < 4; i++)
                ldsm_x4(af[i][0], af[i][1], af[i][2], af[i][3],
                        aHi + i * (16 * 80) + kb);
#pragma unroll
            for (int jp = 0; jp < 4; jp++)
                ldsm_x4(bf[2 * jp][0], bf[2 * jp][1],
                        bf[2 * jp + 1][0], bf[2 * jp + 1][1],
                        bHi + jp * (16 * 80) + kb);
#pragma unroll
            for (int i = 0; i < 4; i++)
#pragma unroll
                for (int j = 0; j < 8; j++)
                    mma16816(acc[i][j], af[i], bf[j]);
        }

        if (c + 2 < 32) {
            const int ws = (stage + 2) % 3;
            const unsigned st = sbase + (unsigned)ws * GSTAGE;
            const int kc = (c + 2) * 32;
            CP_ASYNC16(st + soA, pA + kc);
            CP_ASYNC16(st + soA + 64 * 80, pA + (size_t)64 * DM + kc);
#pragma unroll
            for (int r = 0; r < 4; r++)
                CP_ASYNC16(st + soB + r * (64 * 80), pB + (size_t)(64 * r) * DM + kc);
            CP_COMMIT();
        }
        stage = (stage + 1) % 3;
    }

    const int g = lane >> 2;
    const int c = lane & 3;
#pragma unroll
    for (int i = 0; i < 4; i++) {
#pragma unroll
        for (int j = 0; j < 8; j++) {
            const int rm = m0 + warp_m + i * 16 + g;
            const int cn = n0 + warp_n + j * 8 + 2 * c;
            const float2 bv = *(const float2*)(bias + cn);
            float v00 = acc[i][j][0] + bv.x, v01 = acc[i][j][1] + bv.y;
            float v10 = acc[i][j][2] + bv.x, v11 = acc[i][j][3] + bv.y;
            if (MODE == 0) {
                const int which = cn >> 10;           // 0=Q,1=K,2=V
                const int head  = (cn & 1023) >> 6;
                const int hcol  = cn & 63;
                const int b0r = rm >> 11, s0 = rm & 2047;
                const int b1r = (rm + 8) >> 11, s1 = (rm + 8) & 2047;
                const size_t i0 = (((size_t)(b0r * NH + head)) * SEQ + s0) * DH + hcol;
                const size_t i1 = (((size_t)(b1r * NH + head)) * SEQ + s1) * DH + hcol;
                __half* hp;
                if (which == 0) { hp = g_Qhi;
                                  v00 *= 0.125f; v01 *= 0.125f;
                                  v10 *= 0.125f; v11 *= 0.125f; }
                else if (which == 1) hp = g_Khi;
                else                 hp = g_Vhi;
                *(unsigned*)(hp + i0) =
                    pack_h2(__float2half_rn(v00), __float2half_rn(v01));
                *(unsigned*)(hp + i1) =
                    pack_h2(__float2half_rn(v10), __float2half_rn(v11));
            } else {
                *(float2*)(Cout + (size_t)rm * DM + cn) = make_float2(v00, v01);
                *(float2*)(Cout + (size_t)(rm + 8) * DM + cn) = make_float2(v10, v11);
            }
        }
    }
}

// ---------------------------------------------------------------------------
// Tensor-core causal flash attention, single-term fp16 (unchanged from R10).
// ---------------------------------------------------------------------------
#define FROWB 144
#define FTILE (64 * FROWB)          // 9216 (64-row tile)
#define FSTAGE (2 * FTILE)          // Khi|Vhi = 18432
#define FLASH_SMEM (2 * FSTAGE)     // 36864

__global__ void __launch_bounds__(256) flash_tc_kernel()
{
    extern __shared__ __align__(16) char fsm[];

    const int tid  = threadIdx.x;
    const int lane = tid & 31;
    const int wid  = tid >> 5;
    const int warp_m = wid << 4;
    const int qt = (SEQ / 128 - 1) - blockIdx.x;
    const int h  = blockIdx.y;
    const int b  = blockIdx.z;
    const int q0 = qt << 7;
    const int bh = b * NH + h;
    const size_t base = (size_t)bh * SEQ * DH;
    const unsigned sb = smem_to_u32(fsm);

    // ---- stage Q (128 rows, fp16) and extract fragments ----
    {
        const __half* qh = g_Qhi + base + (size_t)q0 * DH;
#pragma unroll
        for (int r = 0; r < 4; r++) {
            const int cc = tid + (r << 8);
            const int row = cc >> 3, ch = cc & 7;
            *(uint4*)(fsm + row * FROWB + ch * 16) =
                *(const uint4*)(qh + row * DH + ch * 8);
        }
    }
    __syncthreads();
    unsigned qf[4][4];
    {
        const unsigned qa = sb + (warp_m + (lane & 15)) * FROWB + ((lane >> 4) << 4);
#pragma unroll
        for (int t = 0; t < 4; t++)
            ldsm_x4(qf[t][0], qf[t][1], qf[t][2], qf[t][3], qa + t * 32);
    }
    __syncthreads();

    float o[8][4] = {};
    float m0 = -1e30f, m1 = -1e30f, l0 = 0.f, l1 = 0.f;
    const int g  = lane >> 2;
    const int c4 = lane & 3;
    const int row0 = q0 + warp_m + g;
    const int row1 = row0 + 8;

    const unsigned ka0 = sb + ((lane & 7) + ((lane >> 4) << 3)) * FROWB
                            + (((lane >> 3) & 1) << 4);
    const unsigned va0 = sb + FTILE
                            + ((lane & 7) + (((lane >> 3) & 1) << 3)) * FROWB
                            + ((lane >> 4) << 4);

    const int srow = tid >> 3, sch = tid & 7;
    const unsigned sso = srow * FROWB + sch * 16;
    const unsigned sgo = srow * DH + sch * 8;

    const int nkt = (q0 >> 6) + 2;

    // prologue: tile 0 -> stage 0
    {
        const __half* pk = g_Khi + base;
        const __half* pv = g_Vhi + base;
#pragma unroll
        for (int r = 0; r < 2; r++) {
            const unsigned so = sso + r * (32 * FROWB);
            const unsigned go = sgo + r * (32 * DH);
            CP_ASYNC16(sb + so, pk + go);
            CP_ASYNC16(sb + FTILE + so, pv + go);
        }
        CP_COMMIT();
    }

    for (int kt = 0; kt < nkt; kt++) {
        const int k0 = kt << 6;
        if (kt + 1 < nkt) {
            const size_t nb = base + (size_t)((kt + 1) << 6) * DH;
            const unsigned st = sb + ((kt + 1) & 1) * FSTAGE;
            const __half* pk = g_Khi + nb;
            const __half* pv = g_Vhi + nb;
#pragma unroll
            for (int r = 0; r < 2; r++) {
                const unsigned so = sso + r * (32 * FROWB);
                const unsigned go = sgo + r * (32 * DH);
                CP_ASYNC16(st + so, pk + go);
                CP_ASYNC16(st + FTILE + so, pv + go);
            }
            CP_COMMIT();
            CP_WAIT(1);
        } else {
            CP_WAIT(0);
        }
        __syncthreads();

        if (k0 <= q0 + warp_m + 15) {
            const unsigned stof = (kt & 1) * FSTAGE;
            const unsigned ka = ka0 + stof;
            const unsigned va = va0 + stof;

            float s[8][4];
#pragma unroll
            for (int j = 0; j < 8; j++)
#pragma unroll
                for (int x = 0; x < 4; x++) s[j][x] = 0.f;

#pragma unroll
            for (int t = 0; t < 4; t++) {
                unsigned kf[8][2];
#pragma unroll
                for (int jp = 0; jp < 4; jp++)
                    ldsm_x4(kf[2 * jp][0], kf[2 * jp][1],
                            kf[2 * jp + 1][0], kf[2 * jp + 1][1],
                            ka + jp * (16 * FROWB) + t * 32);
#pragma unroll
                for (int j = 0; j < 8; j++) mma16816(s[j], qf[t], kf[j]);
            }

            if (k0 + 63 > q0 + warp_m) {
#pragma unroll
                for (int j = 0; j < 8; j++) {
                    const int col = k0 + 8 * j + 2 * c4;
                    if (col     > row0) s[j][0] = -1e30f;
                    if (col + 1 > row0) s[j][1] = -1e30f;
                    if (col     > row1) s[j][2] = -1e30f;
                    if (col + 1 > row1) s[j][3] = -1e30f;
                }
            }

            float rx0 = -1e30f, rx1 = -1e30f;
#pragma unroll
            for (int j = 0; j < 8; j++) {
                rx0 = fmaxf(rx0, fmaxf(s[j][0], s[j][1]));
                rx1 = fmaxf(rx1, fmaxf(s[j][2], s[j][3]));
            }
            rx0 = fmaxf(rx0, __shfl_xor_sync(0xffffffffu, rx0, 1));
            rx0 = fmaxf(rx0, __shfl_xor_sync(0xffffffffu, rx0, 2));
            rx1 = fmaxf(rx1, __shfl_xor_sync(0xffffffffu, rx1, 1));
            rx1 = fmaxf(rx1, __shfl_xor_sync(0xffffffffu, rx1, 2));
            const float mn0 = fmaxf(m0, rx0), mn1 = fmaxf(m1, rx1);
            const float a0 = __expf(m0 - mn0), a1 = __expf(m1 - mn1);
            float sum0 = 0.f, sum1 = 0.f;
#pragma unroll
            for (int j = 0; j < 8; j++) {
                s[j][0] = __expf(s[j][0] - mn0);
                s[j][1] = __expf(s[j][1] - mn0);
                s[j][2] = __expf(s[j][2] - mn1);
                s[j][3] = __expf(s[j][3] - mn1);
                sum0 += s[j][0] + s[j][1];
                sum1 += s[j][2] + s[j][3];
            }
            sum0 += __shfl_xor_sync(0xffffffffu, sum0, 1);
            sum0 += __shfl_xor_sync(0xffffffffu, sum0, 2);
            sum1 += __shfl_xor_sync(0xffffffffu, sum1, 1);
            sum1 += __shfl_xor_sync(0xffffffffu, sum1, 2);
            l0 = l0 * a0 + sum0;  l1 = l1 * a1 + sum1;
            m0 = mn0;  m1 = mn1;
#pragma unroll
            for (int j = 0; j < 8; j++) {
                o[j][0] *= a0; o[j][1] *= a0; o[j][2] *= a1; o[j][3] *= a1;
            }

#pragma unroll
            for (int t = 0; t < 4; t++) {
                unsigned ahi[4];
                ahi[0] = pack_h2(__float2half_rn(s[2 * t][0]),
                                 __float2half_rn(s[2 * t][1]));
                ahi[1] = pack_h2(__float2half_rn(s[2 * t][2]),
                                 __float2half_rn(s[2 * t][3]));
                ahi[2] = pack_h2(__float2half_rn(s[2 * t + 1][0]),
                                 __float2half_rn(s[2 * t + 1][1]));
                ahi[3] = pack_h2(__float2half_rn(s[2 * t + 1][2]),
                                 __float2half_rn(s[2 * t + 1][3]));
#pragma unroll
                for (int j2 = 0; j2 < 4; j2++) {
                    unsigned v0, v1, v2, v3;
                    ldsm_x4_t(v0, v1, v2, v3, va + t * (16 * FROWB) + j2 * 32);
                    unsigned bA[2] = {v0, v1}, bB[2] = {v2, v3};
                    mma16816(o[2 * j2],     ahi, bA);
                    mma16816(o[2 * j2 + 1], ahi, bB);
                }
            }
        }
        __syncthreads();
    }

    // epilogue: normalize, single fp16 store to g_ahi [B,S,DM]
    const float i0 = 1.f / l0, i1 = 1.f / l1;
    const int tok0 = b * SEQ + q0 + warp_m + g;
    const int tok1 = tok0 + 8;
    const int colb = h * DH + 2 * c4;
#pragma unroll
    for (int j = 0; j < 8; j++) {
        *(unsigned*)(g_ahi + (size_t)tok0 * DM + colb + 8 * j) =
            pack_h2(__float2half_rn(o[j][0] * i0), __float2half_rn(o[j][1] * i0));
        *(unsigned*)(g_ahi + (size_t)tok1 * DM + colb + 8 * j) =
            pack_h2(__float2half_rn(o[j][2] * i1), __float2half_rn(o[j][3] * i1));
    }
}

// ---------------------------------------------------------------------------
extern "C" void kernel_launch(void* const* d_in, const int* in_sizes, int n_in,
                              void* d_out, int out_size)
{
    (void)in_sizes; (void)n_in; (void)out_size;
    const float* x    = (const float*)d_in[0];
    const float* Wqkv = (const float*)d_in[1];
    const float* bqkv = (const float*)d_in[2];
    const float* Wo   = (const float*)d_in[3];
    const float* bo   = (const float*)d_in[4];
    float* out = (float*)d_out;

    cudaFuncSetAttribute(tc_gemm_kernel<0>,
                         cudaFuncAttributeMaxDynamicSharedMemorySize, GEMM_SMEM);
    cudaFuncSetAttribute(tc_gemm_kernel<1>,
                         cudaFuncAttributeMaxDynamicSharedMemorySize, GEMM_SMEM);
    cudaFuncSetAttribute(flash_tc_kernel,
                         cudaFuncAttributeMaxDynamicSharedMemorySize, FLASH_SMEM);

    split_kernel<<<(TOKENS * DM / 4 + 255) / 256, 256>>>(x,    0, TOKENS * DM / 4);
    split_kernel<<<(3 * DM * DM / 4 + 255) / 256, 256>>>(Wqkv, 1, 3 * DM * DM / 4);
    split_kernel<<<(DM * DM / 4 + 255) / 256, 256>>>(Wo,       2, DM * DM / 4);

    // QKV: N=3072 -> grid.x = 12; M=8192 -> grid.y = 64
    tc_gemm_kernel<0><<<dim3(3 * DM / 256, TOKENS / 128), 256, GEMM_SMEM>>>(bqkv, nullptr);

    flash_tc_kernel<<<dim3(SEQ / 128, NH, BATCH), 256, FLASH_SMEM>>>();

    // O-proj: N=1024 -> grid.x = 4; M=8192 -> grid.y = 64
    tc_gemm_kernel<1><<<dim3(DM / 256, TOKENS / 128), 256, GEMM_SMEM>>>(bo, out);
}

// round 12
// speedup vs baseline: 1.0450x; 1.0450x over previous
#include <cuda_runtime.h>
#include <cuda_fp16.h>
#include <math.h>

#define DM     1024
#define NH     16
#define DH     64
#define BATCH  4
#define SEQ    2048
#define TOKENS (BATCH * SEQ)

// ---------------------------------------------------------------------------
// Scratch (static device memory). Fully single-term fp16 scheme.
// ---------------------------------------------------------------------------
__device__ __align__(16) __half g_xhi[TOKENS * DM];
__device__ __align__(16) __half g_wqkv_hi[3 * DM * DM];
__device__ __align__(16) __half g_wo_hi[DM * DM];
__device__ __align__(16) __half g_ahi[TOKENS * DM];
__device__ __align__(16) __half g_Qhi[TOKENS * DM];   // pre-scaled by 0.125
__device__ __align__(16) __half g_Khi[TOKENS * DM];
__device__ __align__(16) __half g_Vhi[TOKENS * DM];

// ---------------------------------------------------------------------------
// helpers
// ---------------------------------------------------------------------------
__device__ __forceinline__ unsigned smem_to_u32(const void* p) {
    unsigned a;
    asm("{ .reg .u64 t; cvta.to.shared.u64 t, %1; cvt.u32.u64 %0, t; }"
        : "=r"(a) : "l"(p));
    return a;
}

#define CP_ASYNC16(saddr, gptr) \
    asm volatile("cp.async.cg.shared.global [%0], [%1], 16;" \
                 :: "r"((unsigned)(saddr)), "l"(gptr))
#define CP_COMMIT() asm volatile("cp.async.commit_group;" ::: "memory")
#define CP_WAIT(n)  asm volatile("cp.async.wait_group %0;" :: "n"(n) : "memory")

__device__ __forceinline__ void ldsm_x4(unsigned& r0, unsigned& r1,
                                        unsigned& r2, unsigned& r3,
                                        unsigned addr) {
    asm volatile("ldmatrix.sync.aligned.m8n8.x4.shared.b16 {%0,%1,%2,%3}, [%4];"
                 : "=r"(r0), "=r"(r1), "=r"(r2), "=r"(r3) : "r"(addr));
}

__device__ __forceinline__ void ldsm_x4_t(unsigned& r0, unsigned& r1,
                                          unsigned& r2, unsigned& r3,
                                          unsigned addr) {
    asm volatile("ldmatrix.sync.aligned.m8n8.x4.trans.shared.b16 {%0,%1,%2,%3}, [%4];"
                 : "=r"(r0), "=r"(r1), "=r"(r2), "=r"(r3) : "r"(addr));
}

__device__ __forceinline__ void mma16816(float* d, const unsigned* a,
                                         const unsigned* b) {
    asm volatile(
        "mma.sync.aligned.m16n8k16.row.col.f32.f16.f16.f32 "
        "{%0,%1,%2,%3}, {%4,%5,%6,%7}, {%8,%9}, {%0,%1,%2,%3};"
        : "+f"(d[0]), "+f"(d[1]), "+f"(d[2]), "+f"(d[3])
        : "r"(a[0]), "r"(a[1]), "r"(a[2]), "r"(a[3]), "r"(b[0]), "r"(b[1]));
}

__device__ __forceinline__ unsigned pack_h2(__half a, __half b) {
    __half2 t = __halves2half2(a, b);
    return *(unsigned*)&t;
}

// ---------------------------------------------------------------------------
// fp32 -> fp16 convert. mode 0: x ; mode 1: Wqkv ; mode 2: Wo
// ---------------------------------------------------------------------------
__global__ void __launch_bounds__(256) split_kernel(
    const float* __restrict__ src, int mode, int n4)
{
    int i = blockIdx.x * blockDim.x + threadIdx.x;
    if (i >= n4) return;
    float4 v = ((const float4*)src)[i];
    __half* hp = (mode == 0) ? g_xhi : (mode == 1) ? g_wqkv_hi : g_wo_hi;
    ((unsigned*)hp)[2 * i] =
        pack_h2(__float2half_rn(v.x), __float2half_rn(v.y));
    ((unsigned*)hp)[2 * i + 1] =
        pack_h2(__float2half_rn(v.z), __float2half_rn(v.w));
}

// ---------------------------------------------------------------------------
// Tensor-core GEMM (R10 proven config): C = A·B^T + bias. K=1024.
// CTA 128x128, 8 warps each 32x64, BK=32, 3-stage cp.async, 2 CTA/SM.
// MODE 0: A=xhi, B=Wqkv -> Q(fp16, scaled 0.125), K, V in [B,H,S,DH]
// MODE 1: A=ahi, B=Wo  -> fp32 row-major Cout
// ---------------------------------------------------------------------------
#define GTILE  10240                 // 128 rows x 80B pitch
#define GSTAGE (2 * GTILE)           // A|B = 20480
#define GEMM_SMEM (3 * GSTAGE)       // 61440 (3 stages)

template <int MODE>
__global__ void __launch_bounds__(256, 2) tc_gemm_kernel(
    const float* __restrict__ bias, float* __restrict__ Cout)
{
    extern __shared__ __align__(16) char gsm[];

    const int tid  = threadIdx.x;
    const int lane = tid & 31;
    const int wid  = tid >> 5;
    const int n0 = blockIdx.x << 7;
    const int m0 = blockIdx.y << 7;
    const int warp_m = (wid & 3) << 5;   // 0,32,64,96
    const int warp_n = (wid >> 2) << 6;  // 0,64
    const unsigned sbase = smem_to_u32(gsm);

    const __half* Ahi = (MODE == 0) ? g_xhi : g_ahi;
    const __half* Bhi = (MODE == 0) ? g_wqkv_hi : g_wo_hi;

    const int rowA = tid >> 2;
    const int quad = tid & 3;
    const __half* pA0 = Ahi + (size_t)(m0 + rowA) * DM + quad * 8;
    const __half* pA1 = pA0 + (size_t)64 * DM;
    const __half* pB0 = Bhi + (size_t)(n0 + rowA) * DM + quad * 8;
    const __half* pB1 = pB0 + (size_t)64 * DM;
    const unsigned so0 = rowA * 80 + quad * 16;
    const unsigned so1 = so0 + 64 * 80;

    const unsigned aHi0 = sbase + (warp_m + (lane & 15)) * 80 + ((lane >> 4) << 4);
    const unsigned bRow = warp_n + ((lane >> 4) << 3) + (lane & 7);
    const unsigned bHi0 = sbase + GTILE + bRow * 80 + (((lane >> 3) & 1) << 4);

    float acc[2][8][4] = {};

    // prologue: chunks 0,1 -> stages 0,1
#pragma unroll
    for (int p = 0; p < 2; p++) {
        const unsigned st = sbase + p * GSTAGE;
        const int kc = p * 32;
        CP_ASYNC16(st + so0, pA0 + kc);
        CP_ASYNC16(st + so1, pA1 + kc);
        CP_ASYNC16(st + GTILE + so0, pB0 + kc);
        CP_ASYNC16(st + GTILE + so1, pB1 + kc);
        CP_COMMIT();
    }

    int stage = 0;
    for (int c = 0; c < 32; c++) {
        if (c <= 29) { CP_WAIT(1); } else { CP_WAIT(0); }
        __syncthreads();

        const unsigned stof = (unsigned)stage * GSTAGE;
        const unsigned aHi = aHi0 + stof;
        const unsigned bHi = bHi0 + stof;

#pragma unroll
        for (int ks2 = 0; ks2 < 2; ks2++) {
            const unsigned kb = ks2 << 5;
            unsigned a_hi[2][4], bf[8][2];
#pragma unroll
            for (int i = 0; i < 2; i++)
                ldsm_x4(a_hi[i][0], a_hi[i][1], a_hi[i][2], a_hi[i][3],
                        aHi + i * (16 * 80) + kb);
#pragma unroll
            for (int jp = 0; jp < 4; jp++)
                ldsm_x4(bf[2 * jp][0], bf[2 * jp][1],
                        bf[2 * jp + 1][0], bf[2 * jp + 1][1],
                        bHi + jp * (16 * 80) + kb);
#pragma unroll
            for (int i = 0; i < 2; i++)
#pragma unroll
                for (int j = 0; j < 8; j++)
                    mma16816(acc[i][j], a_hi[i], bf[j]);
        }

        if (c + 2 < 32) {
            const int ws = (stage + 2) % 3;
            const unsigned st = sbase + (unsigned)ws * GSTAGE;
            const int kc = (c + 2) * 32;
            CP_ASYNC16(st + so0, pA0 + kc);
            CP_ASYNC16(st + so1, pA1 + kc);
            CP_ASYNC16(st + GTILE + so0, pB0 + kc);
            CP_ASYNC16(st + GTILE + so1, pB1 + kc);
            CP_COMMIT();
        }
        stage = (stage + 1) % 3;
    }

    const int g = lane >> 2;
    const int c = lane & 3;
#pragma unroll
    for (int i = 0; i < 2; i++) {
#pragma unroll
        for (int j = 0; j < 8; j++) {
            const int rm = m0 + warp_m + i * 16 + g;
            const int cn = n0 + warp_n + j * 8 + 2 * c;
            const float2 bv = *(const float2*)(bias + cn);
            float v00 = acc[i][j][0] + bv.x, v01 = acc[i][j][1] + bv.y;
            float v10 = acc[i][j][2] + bv.x, v11 = acc[i][j][3] + bv.y;
            if (MODE == 0) {
                const int which = cn >> 10;           // 0=Q,1=K,2=V
                const int head  = (cn & 1023) >> 6;
                const int hcol  = cn & 63;
                const int b0r = rm >> 11, s0 = rm & 2047;
                const int b1r = (rm + 8) >> 11, s1 = (rm + 8) & 2047;
                const size_t i0 = (((size_t)(b0r * NH + head)) * SEQ + s0) * DH + hcol;
                const size_t i1 = (((size_t)(b1r * NH + head)) * SEQ + s1) * DH + hcol;
                __half* hp;
                if (which == 0) { hp = g_Qhi;
                                  v00 *= 0.125f; v01 *= 0.125f;
                                  v10 *= 0.125f; v11 *= 0.125f; }
                else if (which == 1) hp = g_Khi;
                else                 hp = g_Vhi;
                *(unsigned*)(hp + i0) =
                    pack_h2(__float2half_rn(v00), __float2half_rn(v01));
                *(unsigned*)(hp + i1) =
                    pack_h2(__float2half_rn(v10), __float2half_rn(v11));
            } else {
                *(float2*)(Cout + (size_t)rm * DM + cn) = make_float2(v00, v01);
                *(float2*)(Cout + (size_t)(rm + 8) * DM + cn) = make_float2(v10, v11);
            }
        }
    }
}

// ---------------------------------------------------------------------------
// Tensor-core causal flash attention, single-term fp16.
// CTA: 256 q-rows of one (b,h); 8 warps x 32 rows -> 128 B/MMA (vs 256 before).
// cp.async double-buffered Khi|Vhi 64-row tiles.
// ---------------------------------------------------------------------------
#define FROWB 144
#define FTILE (64 * FROWB)          // 9216 (64-row tile)
#define FSTAGE (2 * FTILE)          // Khi|Vhi = 18432
#define FLASH_SMEM (2 * FSTAGE)     // 36864 (also holds 256-row Q during setup)

__global__ void __launch_bounds__(256) flash_tc_kernel()
{
    extern __shared__ __align__(16) char fsm[];

    const int tid  = threadIdx.x;
    const int lane = tid & 31;
    const int wid  = tid >> 5;
    const int warp_m = wid << 5;                 // 0..224
    const int qt = (SEQ / 256 - 1) - blockIdx.x; // longest CTAs first
    const int h  = blockIdx.y;
    const int b  = blockIdx.z;
    const int q0 = qt << 8;                      // 256-row q tile
    const int bh = b * NH + h;
    const size_t base = (size_t)bh * SEQ * DH;
    const unsigned sb = smem_to_u32(fsm);

    // ---- stage Q (256 rows x 64 dh, fp16) into the whole buffer ----
    {
        const __half* qh = g_Qhi + base + (size_t)q0 * DH;
#pragma unroll
        for (int r = 0; r < 8; r++) {
            const int cc = tid + (r << 8);
            const int row = cc >> 3, ch = cc & 7;
            *(uint4*)(fsm + row * FROWB + ch * 16) =
                *(const uint4*)(qh + row * DH + ch * 8);
        }
    }
    __syncthreads();
    unsigned qf[2][4][4];   // [row-half i][k-step t]
    {
#pragma unroll
        for (int i = 0; i < 2; i++) {
            const unsigned qa = sb + (warp_m + i * 16 + (lane & 15)) * FROWB
                                   + ((lane >> 4) << 4);
#pragma unroll
            for (int t = 0; t < 4; t++)
                ldsm_x4(qf[i][t][0], qf[i][t][1], qf[i][t][2], qf[i][t][3],
                        qa + t * 32);
        }
    }
    __syncthreads();

    float o[2][8][4] = {};
    float mm[2][2] = {{-1e30f, -1e30f}, {-1e30f, -1e30f}};
    float ll[2][2] = {};
    const int g  = lane >> 2;
    const int c4 = lane & 3;

    const unsigned ka0 = sb + ((lane & 7) + ((lane >> 4) << 3)) * FROWB
                            + (((lane >> 3) & 1) << 4);
    const unsigned va0 = sb + FTILE
                            + ((lane & 7) + (((lane >> 3) & 1) << 3)) * FROWB
                            + ((lane >> 4) << 4);

    const int srow = tid >> 3, sch = tid & 7;
    const unsigned sso = srow * FROWB + sch * 16;
    const unsigned sgo = srow * DH + sch * 8;

    const int nkt = (q0 >> 6) + 4;   // K tiles of 64 covering q0+255

    // prologue: tile 0 -> stage 0
    {
        const __half* pk = g_Khi + base;
        const __half* pv = g_Vhi + base;
#pragma unroll
        for (int r = 0; r < 2; r++) {
            const unsigned so = sso + r * (32 * FROWB);
            const unsigned go = sgo + r * (32 * DH);
            CP_ASYNC16(sb + so, pk + go);
            CP_ASYNC16(sb + FTILE + so, pv + go);
        }
        CP_COMMIT();
    }

    for (int kt = 0; kt < nkt; kt++) {
        const int k0 = kt << 6;
        if (kt + 1 < nkt) {
            const size_t nb = base + (size_t)((kt + 1) << 6) * DH;
            const unsigned st = sb + ((kt + 1) & 1) * FSTAGE;
            const __half* pk = g_Khi + nb;
            const __half* pv = g_Vhi + nb;
#pragma unroll
            for (int r = 0; r < 2; r++) {
                const unsigned so = sso + r * (32 * FROWB);
                const unsigned go = sgo + r * (32 * DH);
                CP_ASYNC16(st + so, pk + go);
                CP_ASYNC16(st + FTILE + so, pv + go);
            }
            CP_COMMIT();
            CP_WAIT(1);
        } else {
            CP_WAIT(0);
        }
        __syncthreads();

        if (k0 <= q0 + warp_m + 31) {   // warp has live rows in this tile
            const unsigned stof = (kt & 1) * FSTAGE;
            const unsigned ka = ka0 + stof;
            const unsigned va = va0 + stof;

            float s[2][8][4];
#pragma unroll
            for (int i = 0; i < 2; i++)
#pragma unroll
                for (int j = 0; j < 8; j++)
#pragma unroll
                    for (int x = 0; x < 4; x++) s[i][j][x] = 0.f;

            // ---- S = Q K^T ----
#pragma unroll
            for (int t = 0; t < 4; t++) {
                unsigned kf[8][2];
#pragma unroll
                for (int jp = 0; jp < 4; jp++)
                    ldsm_x4(kf[2 * jp][0], kf[2 * jp][1],
                            kf[2 * jp + 1][0], kf[2 * jp + 1][1],
                            ka + jp * (16 * FROWB) + t * 32);
#pragma unroll
                for (int i = 0; i < 2; i++)
#pragma unroll
                    for (int j = 0; j < 8; j++)
                        mma16816(s[i][j], qf[i][t], kf[j]);
            }

            // ---- causal mask ----
            if (k0 + 63 > q0 + warp_m) {
#pragma unroll
                for (int i = 0; i < 2; i++) {
                    const int r0 = q0 + warp_m + i * 16 + g;
                    const int r1 = r0 + 8;
#pragma unroll
                    for (int j = 0; j < 8; j++) {
                        const int col = k0 + 8 * j + 2 * c4;
                        if (col     > r0) s[i][j][0] = -1e30f;
                        if (col + 1 > r0) s[i][j][1] = -1e30f;
                        if (col     > r1) s[i][j][2] = -1e30f;
                        if (col + 1 > r1) s[i][j][3] = -1e30f;
                    }
                }
            }

            // ---- online softmax per row-half ----
#pragma unroll
            for (int i = 0; i < 2; i++) {
                float rx0 = -1e30f, rx1 = -1e30f;
#pragma unroll
                for (int j = 0; j < 8; j++) {
                    rx0 = fmaxf(rx0, fmaxf(s[i][j][0], s[i][j][1]));
                    rx1 = fmaxf(rx1, fmaxf(s[i][j][2], s[i][j][3]));
                }
                rx0 = fmaxf(rx0, __shfl_xor_sync(0xffffffffu, rx0, 1));
                rx0 = fmaxf(rx0, __shfl_xor_sync(0xffffffffu, rx0, 2));
                rx1 = fmaxf(rx1, __shfl_xor_sync(0xffffffffu, rx1, 1));
                rx1 = fmaxf(rx1, __shfl_xor_sync(0xffffffffu, rx1, 2));
                const float mn0 = fmaxf(mm[i][0], rx0);
                const float mn1 = fmaxf(mm[i][1], rx1);
                const float a0 = __expf(mm[i][0] - mn0);
                const float a1 = __expf(mm[i][1] - mn1);
                float sum0 = 0.f, sum1 = 0.f;
#pragma unroll
                for (int j = 0; j < 8; j++) {
                    s[i][j][0] = __expf(s[i][j][0] - mn0);
                    s[i][j][1] = __expf(s[i][j][1] - mn0);
                    s[i][j][2] = __expf(s[i][j][2] - mn1);
                    s[i][j][3] = __expf(s[i][j][3] - mn1);
                    sum0 += s[i][j][0] + s[i][j][1];
                    sum1 += s[i][j][2] + s[i][j][3];
                }
                sum0 += __shfl_xor_sync(0xffffffffu, sum0, 1);
                sum0 += __shfl_xor_sync(0xffffffffu, sum0, 2);
                sum1 += __shfl_xor_sync(0xffffffffu, sum1, 1);
                sum1 += __shfl_xor_sync(0xffffffffu, sum1, 2);
                ll[i][0] = ll[i][0] * a0 + sum0;
                ll[i][1] = ll[i][1] * a1 + sum1;
                mm[i][0] = mn0;  mm[i][1] = mn1;
#pragma unroll
                for (int j = 0; j < 8; j++) {
                    o[i][j][0] *= a0; o[i][j][1] *= a0;
                    o[i][j][2] *= a1; o[i][j][3] *= a1;
                }
            }

            // ---- O += P V (V fragments shared by both row-halves) ----
#pragma unroll
            for (int t = 0; t < 4; t++) {
                unsigned ah[2][4];
#pragma unroll
                for (int i = 0; i < 2; i++) {
                    ah[i][0] = pack_h2(__float2half_rn(s[i][2 * t][0]),
                                       __float2half_rn(s[i][2 * t][1]));
                    ah[i][1] = pack_h2(__float2half_rn(s[i][2 * t][2]),
                                       __float2half_rn(s[i][2 * t][3]));
                    ah[i][2] = pack_h2(__float2half_rn(s[i][2 * t + 1][0]),
                                       __float2half_rn(s[i][2 * t + 1][1]));
                    ah[i][3] = pack_h2(__float2half_rn(s[i][2 * t + 1][2]),
                                       __float2half_rn(s[i][2 * t + 1][3]));
                }
#pragma unroll
                for (int j2 = 0; j2 < 4; j2++) {
                    unsigned v0, v1, v2, v3;
                    ldsm_x4_t(v0, v1, v2, v3, va + t * (16 * FROWB) + j2 * 32);
                    unsigned bA[2] = {v0, v1}, bB[2] = {v2, v3};
#pragma unroll
                    for (int i = 0; i < 2; i++) {
                        mma16816(o[i][2 * j2],     ah[i], bA);
                        mma16816(o[i][2 * j2 + 1], ah[i], bB);
                    }
                }
            }
        }
        __syncthreads();
    }

    // ---- epilogue: normalize, fp16 store to g_ahi [B,S,DM] ----
    const int colb = h * DH + 2 * c4;
#pragma unroll
    for (int i = 0; i < 2; i++) {
        const float i0 = 1.f / ll[i][0], i1 = 1.f / ll[i][1];
        const int tok0 = b * SEQ + q0 + warp_m + i * 16 + g;
        const int tok1 = tok0 + 8;
#pragma unroll
        for (int j = 0; j < 8; j++) {
            *(unsigned*)(g_ahi + (size_t)tok0 * DM + colb + 8 * j) =
                pack_h2(__float2half_rn(o[i][j][0] * i0),
                        __float2half_rn(o[i][j][1] * i0));
            *(unsigned*)(g_ahi + (size_t)tok1 * DM + colb + 8 * j) =
                pack_h2(__float2half_rn(o[i][j][2] * i1),
                        __float2half_rn(o[i][j][3] * i1));
        }
    }
}

// ---------------------------------------------------------------------------
extern "C" void kernel_launch(void* const* d_in, const int* in_sizes, int n_in,
                              void* d_out, int out_size)
{
    (void)in_sizes; (void)n_in; (void)out_size;
    const float* x    = (const float*)d_in[0];
    const float* Wqkv = (const float*)d_in[1];
    const float* bqkv = (const float*)d_in[2];
    const float* Wo   = (const float*)d_in[3];
    const float* bo   = (const float*)d_in[4];
    float* out = (float*)d_out;

    cudaFuncSetAttribute(tc_gemm_kernel<0>,
                         cudaFuncAttributeMaxDynamicSharedMemorySize, GEMM_SMEM);
    cudaFuncSetAttribute(tc_gemm_kernel<1>,
                         cudaFuncAttributeMaxDynamicSharedMemorySize, GEMM_SMEM);
    cudaFuncSetAttribute(flash_tc_kernel,
                         cudaFuncAttributeMaxDynamicSharedMemorySize, FLASH_SMEM);

    split_kernel<<<(TOKENS * DM / 4 + 255) / 256, 256>>>(x,    0, TOKENS * DM / 4);
    split_kernel<<<(3 * DM * DM / 4 + 255) / 256, 256>>>(Wqkv, 1, 3 * DM * DM / 4);
    split_kernel<<<(DM * DM / 4 + 255) / 256, 256>>>(Wo,       2, DM * DM / 4);

    tc_gemm_kernel<0><<<dim3(3 * DM / 128, TOKENS / 128), 256, GEMM_SMEM>>>(bqkv, nullptr);

    flash_tc_kernel<<<dim3(SEQ / 256, NH, BATCH), 256, FLASH_SMEM>>>();

    tc_gemm_kernel<1><<<dim3(DM / 128, TOKENS / 128), 256, GEMM_SMEM>>>(bo, out);
}

// round 13
// speedup vs baseline: 1.1446x; 1.0953x over previous
#include <cuda_runtime.h>
#include <cuda_fp16.h>
#include <math.h>

#define DM     1024
#define NH     16
#define DH     64
#define BATCH  4
#define SEQ    2048
#define TOKENS (BATCH * SEQ)

// ---------------------------------------------------------------------------
// Scratch (static device memory). Fully single-term fp16 scheme.
// ---------------------------------------------------------------------------
__device__ __align__(16) __half g_xhi[TOKENS * DM];
__device__ __align__(16) __half g_wqkv_hi[3 * DM * DM];
__device__ __align__(16) __half g_wo_hi[DM * DM];
__device__ __align__(16) __half g_ahi[TOKENS * DM];
__device__ __align__(16) __half g_Qhi[TOKENS * DM];   // pre-scaled by 0.125
__device__ __align__(16) __half g_Khi[TOKENS * DM];
__device__ __align__(16) __half g_Vhi[TOKENS * DM];

// ---------------------------------------------------------------------------
// helpers
// ---------------------------------------------------------------------------
__device__ __forceinline__ unsigned smem_to_u32(const void* p) {
    unsigned a;
    asm("{ .reg .u64 t; cvta.to.shared.u64 t, %1; cvt.u32.u64 %0, t; }"
        : "=r"(a) : "l"(p));
    return a;
}

#define CP_ASYNC16(saddr, gptr) \
    asm volatile("cp.async.cg.shared.global [%0], [%1], 16;" \
                 :: "r"((unsigned)(saddr)), "l"(gptr))
#define CP_COMMIT() asm volatile("cp.async.commit_group;" ::: "memory")
#define CP_WAIT(n)  asm volatile("cp.async.wait_group %0;" :: "n"(n) : "memory")

__device__ __forceinline__ void ldsm_x4(unsigned& r0, unsigned& r1,
                                        unsigned& r2, unsigned& r3,
                                        unsigned addr) {
    asm volatile("ldmatrix.sync.aligned.m8n8.x4.shared.b16 {%0,%1,%2,%3}, [%4];"
                 : "=r"(r0), "=r"(r1), "=r"(r2), "=r"(r3) : "r"(addr));
}

__device__ __forceinline__ void ldsm_x4_t(unsigned& r0, unsigned& r1,
                                          unsigned& r2, unsigned& r3,
                                          unsigned addr) {
    asm volatile("ldmatrix.sync.aligned.m8n8.x4.trans.shared.b16 {%0,%1,%2,%3}, [%4];"
                 : "=r"(r0), "=r"(r1), "=r"(r2), "=r"(r3) : "r"(addr));
}

__device__ __forceinline__ void mma16816(float* d, const unsigned* a,
                                         const unsigned* b) {
    asm volatile(
        "mma.sync.aligned.m16n8k16.row.col.f32.f16.f16.f32 "
        "{%0,%1,%2,%3}, {%4,%5,%6,%7}, {%8,%9}, {%0,%1,%2,%3};"
        : "+f"(d[0]), "+f"(d[1]), "+f"(d[2]), "+f"(d[3])
        : "r"(a[0]), "r"(a[1]), "r"(a[2]), "r"(a[3]), "r"(b[0]), "r"(b[1]));
}

__device__ __forceinline__ unsigned pack_h2(__half a, __half b) {
    __half2 t = __halves2half2(a, b);
    return *(unsigned*)&t;
}

// ---------------------------------------------------------------------------
// Fused fp32 -> fp16 convert for x | Wqkv | Wo in ONE launch.
// ---------------------------------------------------------------------------
#define N4X (TOKENS * DM / 4)
#define N4W (3 * DM * DM / 4)
#define N4O (DM * DM / 4)

__global__ void __launch_bounds__(256) split_all_kernel(
    const float* __restrict__ x, const float* __restrict__ wqkv,
    const float* __restrict__ wo)
{
    int i = blockIdx.x * blockDim.x + threadIdx.x;
    const float* src;
    __half* dst;
    int off;
    if (i < N4X)            { src = x;    dst = g_xhi;     off = i; }
    else if (i < N4X + N4W) { src = wqkv; dst = g_wqkv_hi; off = i - N4X; }
    else if (i < N4X + N4W + N4O)
                            { src = wo;   dst = g_wo_hi;   off = i - N4X - N4W; }
    else return;
    float4 v = ((const float4*)src)[off];
    ((unsigned*)dst)[2 * off] =
        pack_h2(__float2half_rn(v.x), __float2half_rn(v.y));
    ((unsigned*)dst)[2 * off + 1] =
        pack_h2(__float2half_rn(v.z), __float2half_rn(v.w));
}

// ---------------------------------------------------------------------------
// Tensor-core GEMM, single-term fp16: C = A·B^T + bias. K=1024.
// CTA 128x128, 8 warps each 32x64, BK=64 (16 chunks), 3-stage cp.async,
// one __syncthreads per chunk, 2 CTA/SM.
// MODE 0: A=xhi, B=Wqkv -> Q(fp16, scaled 0.125), K, V in [B,H,S,DH]
// MODE 1: A=ahi, B=Wo  -> fp32 row-major Cout
// ---------------------------------------------------------------------------
#define GPITCH 144                    // 64 fp16 = 128B data + 16B pad
#define GTILE  (128 * GPITCH)         // 18432
#define GSTAGE (2 * GTILE)            // A|B = 36864
#define GEMM_SMEM (3 * GSTAGE)        // 110592 (3 stages)

template <int MODE>
__global__ void __launch_bounds__(256, 2) tc_gemm_kernel(
    const float* __restrict__ bias, float* __restrict__ Cout)
{
    extern __shared__ __align__(16) char gsm[];

    const int tid  = threadIdx.x;
    const int lane = tid & 31;
    const int wid  = tid >> 5;
    const int n0 = blockIdx.x << 7;
    const int m0 = blockIdx.y << 7;
    const int warp_m = (wid & 3) << 5;   // 0,32,64,96
    const int warp_n = (wid >> 2) << 6;  // 0,64
    const unsigned sbase = smem_to_u32(gsm);

    const __half* Ahi = (MODE == 0) ? g_xhi : g_ahi;
    const __half* Bhi = (MODE == 0) ? g_wqkv_hi : g_wo_hi;

    // staging: rows srow+32r (r=0..3), 16B chunk sch, for A and B
    const int srow = tid >> 3;           // 0..31
    const int sch  = tid & 7;
    const __half* pA = Ahi + (size_t)(m0 + srow) * DM + sch * 8;
    const __half* pB = Bhi + (size_t)(n0 + srow) * DM + sch * 8;
    const unsigned soA = srow * GPITCH + sch * 16;
    const unsigned soB = GTILE + srow * GPITCH + sch * 16;

    const unsigned aHi0 = sbase + (warp_m + (lane & 15)) * GPITCH
                               + ((lane >> 4) << 4);
    const unsigned bRow = warp_n + ((lane >> 4) << 3) + (lane & 7);
    const unsigned bHi0 = sbase + GTILE + bRow * GPITCH
                               + (((lane >> 3) & 1) << 4);

    float acc[2][8][4] = {};

    // prologue: chunks 0,1 -> stages 0,1
#pragma unroll
    for (int p = 0; p < 2; p++) {
        const unsigned st = sbase + p * GSTAGE;
        const int kc = p * 64;
#pragma unroll
        for (int r = 0; r < 4; r++) {
            CP_ASYNC16(st + soA + r * (32 * GPITCH), pA + (size_t)(32 * r) * DM + kc);
            CP_ASYNC16(st + soB + r * (32 * GPITCH), pB + (size_t)(32 * r) * DM + kc);
        }
        CP_COMMIT();
    }

    int stage = 0;
    for (int c = 0; c < 16; c++) {
        if (c <= 13) { CP_WAIT(1); } else { CP_WAIT(0); }
        __syncthreads();

        const unsigned stof = (unsigned)stage * GSTAGE;
        const unsigned aHi = aHi0 + stof;
        const unsigned bHi = bHi0 + stof;

#pragma unroll
        for (int ks = 0; ks < 4; ks++) {
            const unsigned kb = ks << 5;     // 16 fp16 = 32 bytes
            unsigned a_hi[2][4], bf[8][2];
#pragma unroll
            for (int i = 0; i < 2; i++)
                ldsm_x4(a_hi[i][0], a_hi[i][1], a_hi[i][2], a_hi[i][3],
                        aHi + i * (16 * GPITCH) + kb);
#pragma unroll
            for (int jp = 0; jp < 4; jp++)
                ldsm_x4(bf[2 * jp][0], bf[2 * jp][1],
                        bf[2 * jp + 1][0], bf[2 * jp + 1][1],
                        bHi + jp * (16 * GPITCH) + kb);
#pragma unroll
            for (int i = 0; i < 2; i++)
#pragma unroll
                for (int j = 0; j < 8; j++)
                    mma16816(acc[i][j], a_hi[i], bf[j]);
        }

        if (c + 2 < 16) {
            const int ws = (stage + 2) % 3;
            const unsigned st = sbase + (unsigned)ws * GSTAGE;
            const int kc = (c + 2) * 64;
#pragma unroll
            for (int r = 0; r < 4; r++) {
                CP_ASYNC16(st + soA + r * (32 * GPITCH),
                           pA + (size_t)(32 * r) * DM + kc);
                CP_ASYNC16(st + soB + r * (32 * GPITCH),
                           pB + (size_t)(32 * r) * DM + kc);
            }
            CP_COMMIT();
        }
        stage = (stage + 1) % 3;
    }

    const int g = lane >> 2;
    const int c = lane & 3;
#pragma unroll
    for (int i = 0; i < 2; i++) {
#pragma unroll
        for (int j = 0; j < 8; j++) {
            const int rm = m0 + warp_m + i * 16 + g;
            const int cn = n0 + warp_n + j * 8 + 2 * c;
            const float2 bv = *(const float2*)(bias + cn);
            float v00 = acc[i][j][0] + bv.x, v01 = acc[i][j][1] + bv.y;
            float v10 = acc[i][j][2] + bv.x, v11 = acc[i][j][3] + bv.y;
            if (MODE == 0) {
                const int which = cn >> 10;           // 0=Q,1=K,2=V
                const int head  = (cn & 1023) >> 6;
                const int hcol  = cn & 63;
                const int b0r = rm >> 11, s0 = rm & 2047;
                const int b1r = (rm + 8) >> 11, s1 = (rm + 8) & 2047;
                const size_t i0 = (((size_t)(b0r * NH + head)) * SEQ + s0) * DH + hcol;
                const size_t i1 = (((size_t)(b1r * NH + head)) * SEQ + s1) * DH + hcol;
                __half* hp;
                if (which == 0) { hp = g_Qhi;
                                  v00 *= 0.125f; v01 *= 0.125f;
                                  v10 *= 0.125f; v11 *= 0.125f; }
                else if (which == 1) hp = g_Khi;
                else                 hp = g_Vhi;
                *(unsigned*)(hp + i0) =
                    pack_h2(__float2half_rn(v00), __float2half_rn(v01));
                *(unsigned*)(hp + i1) =
                    pack_h2(__float2half_rn(v10), __float2half_rn(v11));
            } else {
                *(float2*)(Cout + (size_t)rm * DM + cn) = make_float2(v00, v01);
                *(float2*)(Cout + (size_t)(rm + 8) * DM + cn) = make_float2(v10, v11);
            }
        }
    }
}

// ---------------------------------------------------------------------------
// Tensor-core causal flash attention, single-term fp16 (R10 proven version).
// CTA: 128 q-rows of one (b,h); 8 warps x 16 rows; K-tiles of 64.
// ---------------------------------------------------------------------------
#define FROWB 144
#define FTILE (64 * FROWB)          // 9216 (64-row tile)
#define FSTAGE (2 * FTILE)          // Khi|Vhi = 18432
#define FLASH_SMEM (2 * FSTAGE)     // 36864

__global__ void __launch_bounds__(256) flash_tc_kernel()
{
    extern __shared__ __align__(16) char fsm[];

    const int tid  = threadIdx.x;
    const int lane = tid & 31;
    const int wid  = tid >> 5;
    const int warp_m = wid << 4;
    const int qt = (SEQ / 128 - 1) - blockIdx.x;
    const int h  = blockIdx.y;
    const int b  = blockIdx.z;
    const int q0 = qt << 7;
    const int bh = b * NH + h;
    const size_t base = (size_t)bh * SEQ * DH;
    const unsigned sb = smem_to_u32(fsm);

    // ---- stage Q (128 rows, fp16) and extract fragments ----
    {
        const __half* qh = g_Qhi + base + (size_t)q0 * DH;
#pragma unroll
        for (int r = 0; r < 4; r++) {
            const int cc = tid + (r << 8);
            const int row = cc >> 3, ch = cc & 7;
            *(uint4*)(fsm + row * FROWB + ch * 16) =
                *(const uint4*)(qh + row * DH + ch * 8);
        }
    }
    __syncthreads();
    unsigned qf[4][4];
    {
        const unsigned qa = sb + (warp_m + (lane & 15)) * FROWB + ((lane >> 4) << 4);
#pragma unroll
        for (int t = 0; t < 4; t++)
            ldsm_x4(qf[t][0], qf[t][1], qf[t][2], qf[t][3], qa + t * 32);
    }
    __syncthreads();

    float o[8][4] = {};
    float m0 = -1e30f, m1 = -1e30f, l0 = 0.f, l1 = 0.f;
    const int g  = lane >> 2;
    const int c4 = lane & 3;
    const int row0 = q0 + warp_m + g;
    const int row1 = row0 + 8;

    const unsigned ka0 = sb + ((lane & 7) + ((lane >> 4) << 3)) * FROWB
                            + (((lane >> 3) & 1) << 4);
    const unsigned va0 = sb + FTILE
                            + ((lane & 7) + (((lane >> 3) & 1) << 3)) * FROWB
                            + ((lane >> 4) << 4);

    const int srow = tid >> 3, sch = tid & 7;
    const unsigned sso = srow * FROWB + sch * 16;
    const unsigned sgo = srow * DH + sch * 8;

    const int nkt = (q0 >> 6) + 2;

    // prologue: tile 0 -> stage 0
    {
        const __half* pk = g_Khi + base;
        const __half* pv = g_Vhi + base;
#pragma unroll
        for (int r = 0; r < 2; r++) {
            const unsigned so = sso + r * (32 * FROWB);
            const unsigned go = sgo + r * (32 * DH);
            CP_ASYNC16(sb + so, pk + go);
            CP_ASYNC16(sb + FTILE + so, pv + go);
        }
        CP_COMMIT();
    }

    for (int kt = 0; kt < nkt; kt++) {
        const int k0 = kt << 6;
        if (kt + 1 < nkt) {
            const size_t nb = base + (size_t)((kt + 1) << 6) * DH;
            const unsigned st = sb + ((kt + 1) & 1) * FSTAGE;
            const __half* pk = g_Khi + nb;
            const __half* pv = g_Vhi + nb;
#pragma unroll
            for (int r = 0; r < 2; r++) {
                const unsigned so = sso + r * (32 * FROWB);
                const unsigned go = sgo + r * (32 * DH);
                CP_ASYNC16(st + so, pk + go);
                CP_ASYNC16(st + FTILE + so, pv + go);
            }
            CP_COMMIT();
            CP_WAIT(1);
        } else {
            CP_WAIT(0);
        }
        __syncthreads();

        if (k0 <= q0 + warp_m + 15) {
            const unsigned stof = (kt & 1) * FSTAGE;
            const unsigned ka = ka0 + stof;
            const unsigned va = va0 + stof;

            float s[8][4];
#pragma unroll
            for (int j = 0; j < 8; j++)
#pragma unroll
                for (int x = 0; x < 4; x++) s[j][x] = 0.f;

#pragma unroll
            for (int t = 0; t < 4; t++) {
                unsigned kf[8][2];
#pragma unroll
                for (int jp = 0; jp < 4; jp++)
                    ldsm_x4(kf[2 * jp][0], kf[2 * jp][1],
                            kf[2 * jp + 1][0], kf[2 * jp + 1][1],
                            ka + jp * (16 * FROWB) + t * 32);
#pragma unroll
                for (int j = 0; j < 8; j++) mma16816(s[j], qf[t], kf[j]);
            }

            if (k0 + 63 > q0 + warp_m) {
#pragma unroll
                for (int j = 0; j < 8; j++) {
                    const int col = k0 + 8 * j + 2 * c4;
                    if (col     > row0) s[j][0] = -1e30f;
                    if (col + 1 > row0) s[j][1] = -1e30f;
                    if (col     > row1) s[j][2] = -1e30f;
                    if (col + 1 > row1) s[j][3] = -1e30f;
                }
            }

            float rx0 = -1e30f, rx1 = -1e30f;
#pragma unroll
            for (int j = 0; j < 8; j++) {
                rx0 = fmaxf(rx0, fmaxf(s[j][0], s[j][1]));
                rx1 = fmaxf(rx1, fmaxf(s[j][2], s[j][3]));
            }
            rx0 = fmaxf(rx0, __shfl_xor_sync(0xffffffffu, rx0, 1));
            rx0 = fmaxf(rx0, __shfl_xor_sync(0xffffffffu, rx0, 2));
            rx1 = fmaxf(rx1, __shfl_xor_sync(0xffffffffu, rx1, 1));
            rx1 = fmaxf(rx1, __shfl_xor_sync(0xffffffffu, rx1, 2));
            const float mn0 = fmaxf(m0, rx0), mn1 = fmaxf(m1, rx1);
            const float a0 = __expf(m0 - mn0), a1 = __expf(m1 - mn1);
            float sum0 = 0.f, sum1 = 0.f;
#pragma unroll
            for (int j = 0; j < 8; j++) {
                s[j][0] = __expf(s[j][0] - mn0);
                s[j][1] = __expf(s[j][1] - mn0);
                s[j][2] = __expf(s[j][2] - mn1);
                s[j][3] = __expf(s[j][3] - mn1);
                sum0 += s[j][0] + s[j][1];
                sum1 += s[j][2] + s[j][3];
            }
            sum0 += __shfl_xor_sync(0xffffffffu, sum0, 1);
            sum0 += __shfl_xor_sync(0xffffffffu, sum0, 2);
            sum1 += __shfl_xor_sync(0xffffffffu, sum1, 1);
            sum1 += __shfl_xor_sync(0xffffffffu, sum1, 2);
            l0 = l0 * a0 + sum0;  l1 = l1 * a1 + sum1;
            m0 = mn0;  m1 = mn1;
#pragma unroll
            for (int j = 0; j < 8; j++) {
                o[j][0] *= a0; o[j][1] *= a0; o[j][2] *= a1; o[j][3] *= a1;
            }

#pragma unroll
            for (int t = 0; t < 4; t++) {
                unsigned ahi[4];
                ahi[0] = pack_h2(__float2half_rn(s[2 * t][0]),
                                 __float2half_rn(s[2 * t][1]));
                ahi[1] = pack_h2(__float2half_rn(s[2 * t][2]),
                                 __float2half_rn(s[2 * t][3]));
                ahi[2] = pack_h2(__float2half_rn(s[2 * t + 1][0]),
                                 __float2half_rn(s[2 * t + 1][1]));
                ahi[3] = pack_h2(__float2half_rn(s[2 * t + 1][2]),
                                 __float2half_rn(s[2 * t + 1][3]));
#pragma unroll
                for (int j2 = 0; j2 < 4; j2++) {
                    unsigned v0, v1, v2, v3;
                    ldsm_x4_t(v0, v1, v2, v3, va + t * (16 * FROWB) + j2 * 32);
                    unsigned bA[2] = {v0, v1}, bB[2] = {v2, v3};
                    mma16816(o[2 * j2],     ahi, bA);
                    mma16816(o[2 * j2 + 1], ahi, bB);
                }
            }
        }
        __syncthreads();
    }

    // epilogue: normalize, single fp16 store to g_ahi [B,S,DM]
    const float i0 = 1.f / l0, i1 = 1.f / l1;
    const int tok0 = b * SEQ + q0 + warp_m + g;
    const int tok1 = tok0 + 8;
    const int colb = h * DH + 2 * c4;
#pragma unroll
    for (int j = 0; j < 8; j++) {
        *(unsigned*)(g_ahi + (size_t)tok0 * DM + colb + 8 * j) =
            pack_h2(__float2half_rn(o[j][0] * i0), __float2half_rn(o[j][1] * i0));
        *(unsigned*)(g_ahi + (size_t)tok1 * DM + colb + 8 * j) =
            pack_h2(__float2half_rn(o[j][2] * i1), __float2half_rn(o[j][3] * i1));
    }
}

// ---------------------------------------------------------------------------
extern "C" void kernel_launch(void* const* d_in, const int* in_sizes, int n_in,
                              void* d_out, int out_size)
{
    (void)in_sizes; (void)n_in; (void)out_size;
    const float* x    = (const float*)d_in[0];
    const float* Wqkv = (const float*)d_in[1];
    const float* bqkv = (const float*)d_in[2];
    const float* Wo   = (const float*)d_in[3];
    const float* bo   = (const float*)d_in[4];
    float* out = (float*)d_out;

    cudaFuncSetAttribute(tc_gemm_kernel<0>,
                         cudaFuncAttributeMaxDynamicSharedMemorySize, GEMM_SMEM);
    cudaFuncSetAttribute(tc_gemm_kernel<1>,
                         cudaFuncAttributeMaxDynamicSharedMemorySize, GEMM_SMEM);
    cudaFuncSetAttribute(flash_tc_kernel,
                         cudaFuncAttributeMaxDynamicSharedMemorySize, FLASH_SMEM);

    // fused fp32 -> fp16 conversion (x | Wqkv | Wo) in one launch
    split_all_kernel<<<(N4X + N4W + N4O + 255) / 256, 256>>>(x, Wqkv, Wo);

    tc_gemm_kernel<0><<<dim3(3 * DM / 128, TOKENS / 128), 256, GEMM_SMEM>>>(bqkv, nullptr);

    flash_tc_kernel<<<dim3(SEQ / 128, NH, BATCH), 256, FLASH_SMEM>>>();

    tc_gemm_kernel<1><<<dim3(DM / 128, TOKENS / 128), 256, GEMM_SMEM>>>(bo, out);
}

// round 14
// speedup vs baseline: 1.1627x; 1.0158x over previous
#include <cuda_runtime.h>
#include <cuda_fp16.h>
#include <math.h>

#define DM     1024
#define NH     16
#define DH     64
#define BATCH  4
#define SEQ    2048
#define TOKENS (BATCH * SEQ)
#define NSM    148
#define PGRID  (2 * NSM)   // persistent grid: 2 CTAs per SM

// ---------------------------------------------------------------------------
// Scratch (static device memory). Fully single-term fp16 scheme.
// ---------------------------------------------------------------------------
__device__ __align__(16) __half g_xhi[TOKENS * DM];
__device__ __align__(16) __half g_wqkv_hi[3 * DM * DM];
__device__ __align__(16) __half g_wo_hi[DM * DM];
__device__ __align__(16) __half g_ahi[TOKENS * DM];
__device__ __align__(16) __half g_Qhi[TOKENS * DM];   // pre-scaled by 0.125*log2(e)
__device__ __align__(16) __half g_Khi[TOKENS * DM];
__device__ __align__(16) __half g_Vhi[TOKENS * DM];

// ---------------------------------------------------------------------------
// helpers
// ---------------------------------------------------------------------------
__device__ __forceinline__ unsigned smem_to_u32(const void* p) {
    unsigned a;
    asm("{ .reg .u64 t; cvta.to.shared.u64 t, %1; cvt.u32.u64 %0, t; }"
        : "=r"(a) : "l"(p));
    return a;
}

#define CP_ASYNC16(saddr, gptr) \
    asm volatile("cp.async.cg.shared.global [%0], [%1], 16;" \
                 :: "r"((unsigned)(saddr)), "l"(gptr))
#define CP_COMMIT() asm volatile("cp.async.commit_group;" ::: "memory")
#define CP_WAIT(n)  asm volatile("cp.async.wait_group %0;" :: "n"(n) : "memory")

__device__ __forceinline__ void ldsm_x4(unsigned& r0, unsigned& r1,
                                        unsigned& r2, unsigned& r3,
                                        unsigned addr) {
    asm volatile("ldmatrix.sync.aligned.m8n8.x4.shared.b16 {%0,%1,%2,%3}, [%4];"
                 : "=r"(r0), "=r"(r1), "=r"(r2), "=r"(r3) : "r"(addr));
}

__device__ __forceinline__ void ldsm_x4_t(unsigned& r0, unsigned& r1,
                                          unsigned& r2, unsigned& r3,
                                          unsigned addr) {
    asm volatile("ldmatrix.sync.aligned.m8n8.x4.trans.shared.b16 {%0,%1,%2,%3}, [%4];"
                 : "=r"(r0), "=r"(r1), "=r"(r2), "=r"(r3) : "r"(addr));
}

__device__ __forceinline__ void mma16816(float* d, const unsigned* a,
                                         const unsigned* b) {
    asm volatile(
        "mma.sync.aligned.m16n8k16.row.col.f32.f16.f16.f32 "
        "{%0,%1,%2,%3}, {%4,%5,%6,%7}, {%8,%9}, {%0,%1,%2,%3};"
        : "+f"(d[0]), "+f"(d[1]), "+f"(d[2]), "+f"(d[3])
        : "r"(a[0]), "r"(a[1]), "r"(a[2]), "r"(a[3]), "r"(b[0]), "r"(b[1]));
}

__device__ __forceinline__ unsigned pack_h2(__half a, __half b) {
    __half2 t = __halves2half2(a, b);
    return *(unsigned*)&t;
}

__device__ __forceinline__ float ex2f(float x) {
    float r;
    asm("ex2.approx.f32 %0, %1;" : "=f"(r) : "f"(x));
    return r;
}

// ---------------------------------------------------------------------------
// Fused fp32 -> fp16 convert for x | Wqkv | Wo in ONE launch.
// ---------------------------------------------------------------------------
#define N4X (TOKENS * DM / 4)
#define N4W (3 * DM * DM / 4)
#define N4O (DM * DM / 4)

__global__ void __launch_bounds__(256) split_all_kernel(
    const float* __restrict__ x, const float* __restrict__ wqkv,
    const float* __restrict__ wo)
{
    int i = blockIdx.x * blockDim.x + threadIdx.x;
    const float* src;
    __half* dst;
    int off;
    if (i < N4X)            { src = x;    dst = g_xhi;     off = i; }
    else if (i < N4X + N4W) { src = wqkv; dst = g_wqkv_hi; off = i - N4X; }
    else if (i < N4X + N4W + N4O)
                            { src = wo;   dst = g_wo_hi;   off = i - N4X - N4W; }
    else return;
    float4 v = ((const float4*)src)[off];
    ((unsigned*)dst)[2 * off] =
        pack_h2(__float2half_rn(v.x), __float2half_rn(v.y));
    ((unsigned*)dst)[2 * off + 1] =
        pack_h2(__float2half_rn(v.z), __float2half_rn(v.w));
}

// ---------------------------------------------------------------------------
// Tensor-core GEMM, single-term fp16, PERSISTENT tile loop.
// CTA 128x128, 8 warps each 32x64, BK=64 (16 chunks), 3-stage cp.async.
// MODE 0: A=xhi, B=Wqkv (NX=24 tiles wide) -> Q(scaled)/K/V fp16 [B,H,S,DH]
// MODE 1: A=ahi, B=Wo  (NX=8)             -> fp32 row-major Cout
// ---------------------------------------------------------------------------
#define GPITCH 144                    // 64 fp16 = 128B data + 16B pad
#define GTILE  (128 * GPITCH)         // 18432
#define GSTAGE (2 * GTILE)            // A|B = 36864
#define GEMM_SMEM (3 * GSTAGE)        // 110592 (3 stages)

#define QSCALE (0.125f * 1.44269504088896f)   // fold log2(e) for exp2 softmax

template <int MODE, int NX>
__global__ void __launch_bounds__(256, 2) tc_gemm_kernel(
    const float* __restrict__ bias, float* __restrict__ Cout, int ntiles)
{
    extern __shared__ __align__(16) char gsm[];

    const int tid  = threadIdx.x;
    const int lane = tid & 31;
    const int wid  = tid >> 5;
    const int warp_m = (wid & 3) << 5;   // 0,32,64,96
    const int warp_n = (wid >> 2) << 6;  // 0,64
    const unsigned sbase = smem_to_u32(gsm);

    const __half* Ahi = (MODE == 0) ? g_xhi : g_ahi;
    const __half* Bhi = (MODE == 0) ? g_wqkv_hi : g_wo_hi;

    const int srow = tid >> 3;           // 0..31
    const int sch  = tid & 7;
    const unsigned soA = srow * GPITCH + sch * 16;
    const unsigned soB = GTILE + srow * GPITCH + sch * 16;

    const unsigned aHi0 = sbase + (warp_m + (lane & 15)) * GPITCH
                               + ((lane >> 4) << 4);
    const unsigned bRow = warp_n + ((lane >> 4) << 3) + (lane & 7);
    const unsigned bHi0 = sbase + GTILE + bRow * GPITCH
                               + (((lane >> 3) & 1) << 4);

    const int g = lane >> 2;
    const int c = lane & 3;

    for (int tile = blockIdx.x; tile < ntiles; tile += PGRID) {
        const int n0 = (tile % NX) << 7;
        const int m0 = (tile / NX) << 7;

        const __half* pA = Ahi + (size_t)(m0 + srow) * DM + sch * 8;
        const __half* pB = Bhi + (size_t)(n0 + srow) * DM + sch * 8;

        float acc[2][8][4] = {};

        // prologue: chunks 0,1 -> stages 0,1
#pragma unroll
        for (int p = 0; p < 2; p++) {
            const unsigned st = sbase + p * GSTAGE;
            const int kc = p * 64;
#pragma unroll
            for (int r = 0; r < 4; r++) {
                CP_ASYNC16(st + soA + r * (32 * GPITCH),
                           pA + (size_t)(32 * r) * DM + kc);
                CP_ASYNC16(st + soB + r * (32 * GPITCH),
                           pB + (size_t)(32 * r) * DM + kc);
            }
            CP_COMMIT();
        }

        int stage = 0;
        for (int cch = 0; cch < 16; cch++) {
            if (cch <= 13) { CP_WAIT(1); } else { CP_WAIT(0); }
            __syncthreads();

            const unsigned stof = (unsigned)stage * GSTAGE;
            const unsigned aHi = aHi0 + stof;
            const unsigned bHi = bHi0 + stof;

#pragma unroll
            for (int ks = 0; ks < 4; ks++) {
                const unsigned kb = ks << 5;
                unsigned a_hi[2][4], bf[8][2];
#pragma unroll
                for (int i = 0; i < 2; i++)
                    ldsm_x4(a_hi[i][0], a_hi[i][1], a_hi[i][2], a_hi[i][3],
                            aHi + i * (16 * GPITCH) + kb);
#pragma unroll
                for (int jp = 0; jp < 4; jp++)
                    ldsm_x4(bf[2 * jp][0], bf[2 * jp][1],
                            bf[2 * jp + 1][0], bf[2 * jp + 1][1],
                            bHi + jp * (16 * GPITCH) + kb);
#pragma unroll
                for (int i = 0; i < 2; i++)
#pragma unroll
                    for (int j = 0; j < 8; j++)
                        mma16816(acc[i][j], a_hi[i], bf[j]);
            }

            if (cch + 2 < 16) {
                const int ws = (stage + 2) % 3;
                const unsigned st = sbase + (unsigned)ws * GSTAGE;
                const int kc = (cch + 2) * 64;
#pragma unroll
                for (int r = 0; r < 4; r++) {
                    CP_ASYNC16(st + soA + r * (32 * GPITCH),
                               pA + (size_t)(32 * r) * DM + kc);
                    CP_ASYNC16(st + soB + r * (32 * GPITCH),
                               pB + (size_t)(32 * r) * DM + kc);
                }
                CP_COMMIT();
            }
            stage = (stage + 1) % 3;
        }

        // epilogue (registers only)
#pragma unroll
        for (int i = 0; i < 2; i++) {
#pragma unroll
            for (int j = 0; j < 8; j++) {
                const int rm = m0 + warp_m + i * 16 + g;
                const int cn = n0 + warp_n + j * 8 + 2 * c;
                const float2 bv = *(const float2*)(bias + cn);
                float v00 = acc[i][j][0] + bv.x, v01 = acc[i][j][1] + bv.y;
                float v10 = acc[i][j][2] + bv.x, v11 = acc[i][j][3] + bv.y;
                if (MODE == 0) {
                    const int which = cn >> 10;           // 0=Q,1=K,2=V
                    const int head  = (cn & 1023) >> 6;
                    const int hcol  = cn & 63;
                    const int b0r = rm >> 11, s0 = rm & 2047;
                    const int b1r = (rm + 8) >> 11, s1 = (rm + 8) & 2047;
                    const size_t i0 = (((size_t)(b0r * NH + head)) * SEQ + s0) * DH + hcol;
                    const size_t i1 = (((size_t)(b1r * NH + head)) * SEQ + s1) * DH + hcol;
                    __half* hp;
                    if (which == 0) { hp = g_Qhi;
                                      v00 *= QSCALE; v01 *= QSCALE;
                                      v10 *= QSCALE; v11 *= QSCALE; }
                    else if (which == 1) hp = g_Khi;
                    else                 hp = g_Vhi;
                    *(unsigned*)(hp + i0) =
                        pack_h2(__float2half_rn(v00), __float2half_rn(v01));
                    *(unsigned*)(hp + i1) =
                        pack_h2(__float2half_rn(v10), __float2half_rn(v11));
                } else {
                    *(float2*)(Cout + (size_t)rm * DM + cn) = make_float2(v00, v01);
                    *(float2*)(Cout + (size_t)(rm + 8) * DM + cn) = make_float2(v10, v11);
                }
            }
        }
        // protect stage-0/1 smem from next tile's prologue
        __syncthreads();
    }
}

// ---------------------------------------------------------------------------
// Tensor-core causal flash attention, single-term fp16 (log2-domain softmax).
// CTA: 128 q-rows of one (b,h); 8 warps x 16 rows; K-tiles of 64.
// ---------------------------------------------------------------------------
#define FROWB 144
#define FTILE (64 * FROWB)          // 9216 (64-row tile)
#define FSTAGE (2 * FTILE)          // Khi|Vhi = 18432
#define FLASH_SMEM (2 * FSTAGE)     // 36864

__global__ void __launch_bounds__(256) flash_tc_kernel()
{
    extern __shared__ __align__(16) char fsm[];

    const int tid  = threadIdx.x;
    const int lane = tid & 31;
    const int wid  = tid >> 5;
    const int warp_m = wid << 4;
    const int qt = (SEQ / 128 - 1) - blockIdx.x;
    const int h  = blockIdx.y;
    const int b  = blockIdx.z;
    const int q0 = qt << 7;
    const int bh = b * NH + h;
    const size_t base = (size_t)bh * SEQ * DH;
    const unsigned sb = smem_to_u32(fsm);

    // ---- stage Q (128 rows, fp16; pre-scaled by 0.125*log2e) ----
    {
        const __half* qh = g_Qhi + base + (size_t)q0 * DH;
#pragma unroll
        for (int r = 0; r < 4; r++) {
            const int cc = tid + (r << 8);
            const int row = cc >> 3, ch = cc & 7;
            *(uint4*)(fsm + row * FROWB + ch * 16) =
                *(const uint4*)(qh + row * DH + ch * 8);
        }
    }
    __syncthreads();
    unsigned qf[4][4];
    {
        const unsigned qa = sb + (warp_m + (lane & 15)) * FROWB + ((lane >> 4) << 4);
#pragma unroll
        for (int t = 0; t < 4; t++)
            ldsm_x4(qf[t][0], qf[t][1], qf[t][2], qf[t][3], qa + t * 32);
    }
    __syncthreads();

    float o[8][4] = {};
    float m0 = -1e30f, m1 = -1e30f, l0 = 0.f, l1 = 0.f;
    const int g  = lane >> 2;
    const int c4 = lane & 3;
    const int row0 = q0 + warp_m + g;
    const int row1 = row0 + 8;

    const unsigned ka0 = sb + ((lane & 7) + ((lane >> 4) << 3)) * FROWB
                            + (((lane >> 3) & 1) << 4);
    const unsigned va0 = sb + FTILE
                            + ((lane & 7) + (((lane >> 3) & 1) << 3)) * FROWB
                            + ((lane >> 4) << 4);

    const int srow = tid >> 3, sch = tid & 7;
    const unsigned sso = srow * FROWB + sch * 16;
    const unsigned sgo = srow * DH + sch * 8;

    const int nkt = (q0 >> 6) + 2;

    // prologue: tile 0 -> stage 0
    {
        const __half* pk = g_Khi + base;
        const __half* pv = g_Vhi + base;
#pragma unroll
        for (int r = 0; r < 2; r++) {
            const unsigned so = sso + r * (32 * FROWB);
            const unsigned go = sgo + r * (32 * DH);
            CP_ASYNC16(sb + so, pk + go);
            CP_ASYNC16(sb + FTILE + so, pv + go);
        }
        CP_COMMIT();
    }

    for (int kt = 0; kt < nkt; kt++) {
        const int k0 = kt << 6;
        if (kt + 1 < nkt) {
            const size_t nb = base + (size_t)((kt + 1) << 6) * DH;
            const unsigned st = sb + ((kt + 1) & 1) * FSTAGE;
            const __half* pk = g_Khi + nb;
            const __half* pv = g_Vhi + nb;
#pragma unroll
            for (int r = 0; r < 2; r++) {
                const unsigned so = sso + r * (32 * FROWB);
                const unsigned go = sgo + r * (32 * DH);
                CP_ASYNC16(st + so, pk + go);
                CP_ASYNC16(st + FTILE + so, pv + go);
            }
            CP_COMMIT();
            CP_WAIT(1);
        } else {
            CP_WAIT(0);
        }
        __syncthreads();

        if (k0 <= q0 + warp_m + 15) {
            const unsigned stof = (kt & 1) * FSTAGE;
            const unsigned ka = ka0 + stof;
            const unsigned va = va0 + stof;

            float s[8][4];
#pragma unroll
            for (int j = 0; j < 8; j++)
#pragma unroll
                for (int x = 0; x < 4; x++) s[j][x] = 0.f;

#pragma unroll
            for (int t = 0; t < 4; t++) {
                unsigned kf[8][2];
#pragma unroll
                for (int jp = 0; jp < 4; jp++)
                    ldsm_x4(kf[2 * jp][0], kf[2 * jp][1],
                            kf[2 * jp + 1][0], kf[2 * jp + 1][1],
                            ka + jp * (16 * FROWB) + t * 32);
#pragma unroll
                for (int j = 0; j < 8; j++) mma16816(s[j], qf[t], kf[j]);
            }

            if (k0 + 63 > q0 + warp_m) {
#pragma unroll
                for (int j = 0; j < 8; j++) {
                    const int col = k0 + 8 * j + 2 * c4;
                    if (col     > row0) s[j][0] = -1e30f;
                    if (col + 1 > row0) s[j][1] = -1e30f;
                    if (col     > row1) s[j][2] = -1e30f;
                    if (col + 1 > row1) s[j][3] = -1e30f;
                }
            }

            float rx0 = -1e30f, rx1 = -1e30f;
#pragma unroll
            for (int j = 0; j < 8; j++) {
                rx0 = fmaxf(rx0, fmaxf(s[j][0], s[j][1]));
                rx1 = fmaxf(rx1, fmaxf(s[j][2], s[j][3]));
            }
            rx0 = fmaxf(rx0, __shfl_xor_sync(0xffffffffu, rx0, 1));
            rx0 = fmaxf(rx0, __shfl_xor_sync(0xffffffffu, rx0, 2));
            rx1 = fmaxf(rx1, __shfl_xor_sync(0xffffffffu, rx1, 1));
            rx1 = fmaxf(rx1, __shfl_xor_sync(0xffffffffu, rx1, 2));
            const float mn0 = fmaxf(m0, rx0), mn1 = fmaxf(m1, rx1);
            const float a0 = ex2f(m0 - mn0), a1 = ex2f(m1 - mn1);
            float sum0 = 0.f, sum1 = 0.f;
#pragma unroll
            for (int j = 0; j < 8; j++) {
                s[j][0] = ex2f(s[j][0] - mn0);
                s[j][1] = ex2f(s[j][1] - mn0);
                s[j][2] = ex2f(s[j][2] - mn1);
                s[j][3] = ex2f(s[j][3] - mn1);
                sum0 += s[j][0] + s[j][1];
                sum1 += s[j][2] + s[j][3];
            }
            sum0 += __shfl_xor_sync(0xffffffffu, sum0, 1);
            sum0 += __shfl_xor_sync(0xffffffffu, sum0, 2);
            sum1 += __shfl_xor_sync(0xffffffffu, sum1, 1);
            sum1 += __shfl_xor_sync(0xffffffffu, sum1, 2);
            l0 = l0 * a0 + sum0;  l1 = l1 * a1 + sum1;
            m0 = mn0;  m1 = mn1;
#pragma unroll
            for (int j = 0; j < 8; j++) {
                o[j][0] *= a0; o[j][1] *= a0; o[j][2] *= a1; o[j][3] *= a1;
            }

#pragma unroll
            for (int t = 0; t < 4; t++) {
                unsigned ahi[4];
                ahi[0] = pack_h2(__float2half_rn(s[2 * t][0]),
                                 __float2half_rn(s[2 * t][1]));
                ahi[1] = pack_h2(__float2half_rn(s[2 * t][2]),
                                 __float2half_rn(s[2 * t][3]));
                ahi[2] = pack_h2(__float2half_rn(s[2 * t + 1][0]),
                                 __float2half_rn(s[2 * t + 1][1]));
                ahi[3] = pack_h2(__float2half_rn(s[2 * t + 1][2]),
                                 __float2half_rn(s[2 * t + 1][3]));
#pragma unroll
                for (int j2 = 0; j2 < 4; j2++) {
                    unsigned v0, v1, v2, v3;
                    ldsm_x4_t(v0, v1, v2, v3, va + t * (16 * FROWB) + j2 * 32);
                    unsigned bA[2] = {v0, v1}, bB[2] = {v2, v3};
                    mma16816(o[2 * j2],     ahi, bA);
                    mma16816(o[2 * j2 + 1], ahi, bB);
                }
            }
        }
        __syncthreads();
    }

    // epilogue: normalize, single fp16 store to g_ahi [B,S,DM]
    const float i0 = 1.f / l0, i1 = 1.f / l1;
    const int tok0 = b * SEQ + q0 + warp_m + g;
    const int tok1 = tok0 + 8;
    const int colb = h * DH + 2 * c4;
#pragma unroll
    for (int j = 0; j < 8; j++) {
        *(unsigned*)(g_ahi + (size_t)tok0 * DM + colb + 8 * j) =
            pack_h2(__float2half_rn(o[j][0] * i0), __float2half_rn(o[j][1] * i0));
        *(unsigned*)(g_ahi + (size_t)tok1 * DM + colb + 8 * j) =
            pack_h2(__float2half_rn(o[j][2] * i1), __float2half_rn(o[j][3] * i1));
    }
}

// ---------------------------------------------------------------------------
extern "C" void kernel_launch(void* const* d_in, const int* in_sizes, int n_in,
                              void* d_out, int out_size)
{
    (void)in_sizes; (void)n_in; (void)out_size;
    const float* x    = (const float*)d_in[0];
    const float* Wqkv = (const float*)d_in[1];
    const float* bqkv = (const float*)d_in[2];
    const float* Wo   = (const float*)d_in[3];
    const float* bo   = (const float*)d_in[4];
    float* out = (float*)d_out;

    cudaFuncSetAttribute((const void*)tc_gemm_kernel<0, 24>,
                         cudaFuncAttributeMaxDynamicSharedMemorySize, GEMM_SMEM);
    cudaFuncSetAttribute((const void*)tc_gemm_kernel<1, 8>,
                         cudaFuncAttributeMaxDynamicSharedMemorySize, GEMM_SMEM);
    cudaFuncSetAttribute(flash_tc_kernel,
                         cudaFuncAttributeMaxDynamicSharedMemorySize, FLASH_SMEM);

    // fused fp32 -> fp16 conversion (x | Wqkv | Wo) in one launch
    split_all_kernel<<<(N4X + N4W + N4O + 255) / 256, 256>>>(x, Wqkv, Wo);

    // QKV projection: 24 x 64 = 1536 tiles, persistent grid
    tc_gemm_kernel<0, 24><<<PGRID, 256, GEMM_SMEM>>>(bqkv, nullptr, 1536);

    flash_tc_kernel<<<dim3(SEQ / 128, NH, BATCH), 256, FLASH_SMEM>>>();

    // O-projection: 8 x 64 = 512 tiles, persistent grid
    tc_gemm_kernel<1, 8><<<PGRID, 256, GEMM_SMEM>>>(bo, out, 512);
}

// round 15
// speedup vs baseline: 1.1997x; 1.0318x over previous
#include <cuda_runtime.h>
#include <cuda_fp16.h>
#include <math.h>

#define DM     1024
#define NH     16
#define DH     64
#define BATCH  4
#define SEQ    2048
#define TOKENS (BATCH * SEQ)
#define NSM    148
#define PGRID  (2 * NSM)   // persistent grid: 2 CTAs per SM

// ---------------------------------------------------------------------------
// Scratch (static device memory). Fully single-term fp16 scheme.
// ---------------------------------------------------------------------------
__device__ __align__(16) __half g_xhi[TOKENS * DM];
__device__ __align__(16) __half g_wqkv_hi[3 * DM * DM];
__device__ __align__(16) __half g_wo_hi[DM * DM];
__device__ __align__(16) __half g_ahi[TOKENS * DM];
__device__ __align__(16) __half g_Qhi[TOKENS * DM];   // pre-scaled by 0.125*log2(e)
__device__ __align__(16) __half g_Khi[TOKENS * DM];
__device__ __align__(16) __half g_Vhi[TOKENS * DM];

// ---------------------------------------------------------------------------
// helpers
// ---------------------------------------------------------------------------
__device__ __forceinline__ unsigned smem_to_u32(const void* p) {
    unsigned a;
    asm("{ .reg .u64 t; cvta.to.shared.u64 t, %1; cvt.u32.u64 %0, t; }"
        : "=r"(a) : "l"(p));
    return a;
}

#define CP_ASYNC16(saddr, gptr) \
    asm volatile("cp.async.cg.shared.global [%0], [%1], 16;" \
                 :: "r"((unsigned)(saddr)), "l"(gptr))
#define CP_COMMIT() asm volatile("cp.async.commit_group;" ::: "memory")
#define CP_WAIT(n)  asm volatile("cp.async.wait_group %0;" :: "n"(n) : "memory")

__device__ __forceinline__ void ldsm_x4(unsigned& r0, unsigned& r1,
                                        unsigned& r2, unsigned& r3,
                                        unsigned addr) {
    asm volatile("ldmatrix.sync.aligned.m8n8.x4.shared.b16 {%0,%1,%2,%3}, [%4];"
                 : "=r"(r0), "=r"(r1), "=r"(r2), "=r"(r3) : "r"(addr));
}

__device__ __forceinline__ void ldsm_x4_t(unsigned& r0, unsigned& r1,
                                          unsigned& r2, unsigned& r3,
                                          unsigned addr) {
    asm volatile("ldmatrix.sync.aligned.m8n8.x4.trans.shared.b16 {%0,%1,%2,%3}, [%4];"
                 : "=r"(r0), "=r"(r1), "=r"(r2), "=r"(r3) : "r"(addr));
}

__device__ __forceinline__ void mma16816(float* d, const unsigned* a,
                                         const unsigned* b) {
    asm volatile(
        "mma.sync.aligned.m16n8k16.row.col.f32.f16.f16.f32 "
        "{%0,%1,%2,%3}, {%4,%5,%6,%7}, {%8,%9}, {%0,%1,%2,%3};"
        : "+f"(d[0]), "+f"(d[1]), "+f"(d[2]), "+f"(d[3])
        : "r"(a[0]), "r"(a[1]), "r"(a[2]), "r"(a[3]), "r"(b[0]), "r"(b[1]));
}

__device__ __forceinline__ unsigned pack_h2(__half a, __half b) {
    __half2 t = __halves2half2(a, b);
    return *(unsigned*)&t;
}

__device__ __forceinline__ float ex2f(float x) {
    float r;
    asm("ex2.approx.f32 %0, %1;" : "=f"(r) : "f"(x));
    return r;
}

__device__ __forceinline__ unsigned h2exp2u(unsigned x) {
    unsigned r;
    asm("ex2.approx.f16x2 %0, %1;" : "=r"(r) : "r"(x));
    return r;
}

__device__ __forceinline__ unsigned cvt_h2(float lo, float hi) {
    __half2 t = __floats2half2_rn(lo, hi);
    return *(unsigned*)&t;
}

// ---------------------------------------------------------------------------
// Fused fp32 -> fp16 convert for x | Wqkv | Wo, 4-way strided (MLP=4).
// ---------------------------------------------------------------------------
#define N4X (TOKENS * DM / 4)
#define N4W (3 * DM * DM / 4)
#define N4O (DM * DM / 4)
#define N4TOT (N4X + N4W + N4O)
#define SPLIT_BLOCKS 2048

__device__ __forceinline__ void split_one(
    int i, const float* __restrict__ x, const float* __restrict__ wqkv,
    const float* __restrict__ wo)
{
    const float* src;
    __half* dst;
    int off;
    if (i < N4X)            { src = x;    dst = g_xhi;     off = i; }
    else if (i < N4X + N4W) { src = wqkv; dst = g_wqkv_hi; off = i - N4X; }
    else                    { src = wo;   dst = g_wo_hi;   off = i - N4X - N4W; }
    float4 v = ((const float4*)src)[off];
    ((unsigned*)dst)[2 * off]     = cvt_h2(v.x, v.y);
    ((unsigned*)dst)[2 * off + 1] = cvt_h2(v.z, v.w);
}

__global__ void __launch_bounds__(256) split_all_kernel(
    const float* __restrict__ x, const float* __restrict__ wqkv,
    const float* __restrict__ wo)
{
    const int G = SPLIT_BLOCKS * 256;
    for (int i = blockIdx.x * 256 + threadIdx.x; i < N4TOT; i += 4 * G) {
        split_one(i, x, wqkv, wo);
        if (i + G < N4TOT)     split_one(i + G, x, wqkv, wo);
        if (i + 2 * G < N4TOT) split_one(i + 2 * G, x, wqkv, wo);
        if (i + 3 * G < N4TOT) split_one(i + 3 * G, x, wqkv, wo);
    }
}

// ---------------------------------------------------------------------------
// Tensor-core GEMM, single-term fp16, PERSISTENT tile loop (R14 proven).
// CTA 128x128, 8 warps each 32x64, BK=64 (16 chunks), 3-stage cp.async.
// MODE 0: A=xhi, B=Wqkv (NX=24) -> Q(scaled)/K/V fp16 [B,H,S,DH]
// MODE 1: A=ahi, B=Wo  (NX=8)  -> fp32 row-major Cout
// ---------------------------------------------------------------------------
#define GPITCH 144
#define GTILE  (128 * GPITCH)
#define GSTAGE (2 * GTILE)
#define GEMM_SMEM (3 * GSTAGE)

#define QSCALE (0.125f * 1.44269504088896f)

template <int MODE, int NX>
__global__ void __launch_bounds__(256, 2) tc_gemm_kernel(
    const float* __restrict__ bias, float* __restrict__ Cout, int ntiles)
{
    extern __shared__ __align__(16) char gsm[];

    const int tid  = threadIdx.x;
    const int lane = tid & 31;
    const int wid  = tid >> 5;
    const int warp_m = (wid & 3) << 5;
    const int warp_n = (wid >> 2) << 6;
    const unsigned sbase = smem_to_u32(gsm);

    const __half* Ahi = (MODE == 0) ? g_xhi : g_ahi;
    const __half* Bhi = (MODE == 0) ? g_wqkv_hi : g_wo_hi;

    const int srow = tid >> 3;
    const int sch  = tid & 7;
    const unsigned soA = srow * GPITCH + sch * 16;
    const unsigned soB = GTILE + srow * GPITCH + sch * 16;

    const unsigned aHi0 = sbase + (warp_m + (lane & 15)) * GPITCH
                               + ((lane >> 4) << 4);
    const unsigned bRow = warp_n + ((lane >> 4) << 3) + (lane & 7);
    const unsigned bHi0 = sbase + GTILE + bRow * GPITCH
                               + (((lane >> 3) & 1) << 4);

    const int g = lane >> 2;
    const int c = lane & 3;

    for (int tile = blockIdx.x; tile < ntiles; tile += PGRID) {
        const int n0 = (tile % NX) << 7;
        const int m0 = (tile / NX) << 7;

        const __half* pA = Ahi + (size_t)(m0 + srow) * DM + sch * 8;
        const __half* pB = Bhi + (size_t)(n0 + srow) * DM + sch * 8;

        float acc[2][8][4] = {};

#pragma unroll
        for (int p = 0; p < 2; p++) {
            const unsigned st = sbase + p * GSTAGE;
            const int kc = p * 64;
#pragma unroll
            for (int r = 0; r < 4; r++) {
                CP_ASYNC16(st + soA + r * (32 * GPITCH),
                           pA + (size_t)(32 * r) * DM + kc);
                CP_ASYNC16(st + soB + r * (32 * GPITCH),
                           pB + (size_t)(32 * r) * DM + kc);
            }
            CP_COMMIT();
        }

        int stage = 0;
        for (int cch = 0; cch < 16; cch++) {
            if (cch <= 13) { CP_WAIT(1); } else { CP_WAIT(0); }
            __syncthreads();

            const unsigned stof = (unsigned)stage * GSTAGE;
            const unsigned aHi = aHi0 + stof;
            const unsigned bHi = bHi0 + stof;

#pragma unroll
            for (int ks = 0; ks < 4; ks++) {
                const unsigned kb = ks << 5;
                unsigned a_hi[2][4], bf[8][2];
#pragma unroll
                for (int i = 0; i < 2; i++)
                    ldsm_x4(a_hi[i][0], a_hi[i][1], a_hi[i][2], a_hi[i][3],
                            aHi + i * (16 * GPITCH) + kb);
#pragma unroll
                for (int jp = 0; jp < 4; jp++)
                    ldsm_x4(bf[2 * jp][0], bf[2 * jp][1],
                            bf[2 * jp + 1][0], bf[2 * jp + 1][1],
                            bHi + jp * (16 * GPITCH) + kb);
#pragma unroll
                for (int i = 0; i < 2; i++)
#pragma unroll
                    for (int j = 0; j < 8; j++)
                        mma16816(acc[i][j], a_hi[i], bf[j]);
            }

            if (cch + 2 < 16) {
                const int ws = (stage + 2) % 3;
                const unsigned st = sbase + (unsigned)ws * GSTAGE;
                const int kc = (cch + 2) * 64;
#pragma unroll
                for (int r = 0; r < 4; r++) {
                    CP_ASYNC16(st + soA + r * (32 * GPITCH),
                               pA + (size_t)(32 * r) * DM + kc);
                    CP_ASYNC16(st + soB + r * (32 * GPITCH),
                               pB + (size_t)(32 * r) * DM + kc);
                }
                CP_COMMIT();
            }
            stage = (stage + 1) % 3;
        }

#pragma unroll
        for (int i = 0; i < 2; i++) {
#pragma unroll
            for (int j = 0; j < 8; j++) {
                const int rm = m0 + warp_m + i * 16 + g;
                const int cn = n0 + warp_n + j * 8 + 2 * c;
                const float2 bv = *(const float2*)(bias + cn);
                float v00 = acc[i][j][0] + bv.x, v01 = acc[i][j][1] + bv.y;
                float v10 = acc[i][j][2] + bv.x, v11 = acc[i][j][3] + bv.y;
                if (MODE == 0) {
                    const int which = cn >> 10;
                    const int head  = (cn & 1023) >> 6;
                    const int hcol  = cn & 63;
                    const int b0r = rm >> 11, s0 = rm & 2047;
                    const int b1r = (rm + 8) >> 11, s1 = (rm + 8) & 2047;
                    const size_t i0 = (((size_t)(b0r * NH + head)) * SEQ + s0) * DH + hcol;
                    const size_t i1 = (((size_t)(b1r * NH + head)) * SEQ + s1) * DH + hcol;
                    __half* hp;
                    if (which == 0) { hp = g_Qhi;
                                      v00 *= QSCALE; v01 *= QSCALE;
                                      v10 *= QSCALE; v11 *= QSCALE; }
                    else if (which == 1) hp = g_Khi;
                    else                 hp = g_Vhi;
                    *(unsigned*)(hp + i0) = cvt_h2(v00, v01);
                    *(unsigned*)(hp + i1) = cvt_h2(v10, v11);
                } else {
                    *(float2*)(Cout + (size_t)rm * DM + cn) = make_float2(v00, v01);
                    *(float2*)(Cout + (size_t)(rm + 8) * DM + cn) = make_float2(v10, v11);
                }
            }
        }
        __syncthreads();
    }
}

// ---------------------------------------------------------------------------
// Tensor-core causal flash attention, single-term fp16.
// Softmax: log2-domain; P computed with ex2.approx.f16x2 directly in fp16;
// row sums l accumulated via ones-B MMA (consistent with PV numerics).
// CTA: 128 q-rows of one (b,h); 8 warps x 16 rows; K-tiles of 64.
// ---------------------------------------------------------------------------
#define FROWB 144
#define FTILE (64 * FROWB)
#define FSTAGE (2 * FTILE)
#define FLASH_SMEM (2 * FSTAGE)

__global__ void __launch_bounds__(256, 2) flash_tc_kernel()
{
    extern __shared__ __align__(16) char fsm[];

    const int tid  = threadIdx.x;
    const int lane = tid & 31;
    const int wid  = tid >> 5;
    const int warp_m = wid << 4;
    const int qt = (SEQ / 128 - 1) - blockIdx.x;
    const int h  = blockIdx.y;
    const int b  = blockIdx.z;
    const int q0 = qt << 7;
    const int bh = b * NH + h;
    const size_t base = (size_t)bh * SEQ * DH;
    const unsigned sb = smem_to_u32(fsm);

    // ---- stage Q (128 rows, fp16; pre-scaled by 0.125*log2e) ----
    {
        const __half* qh = g_Qhi + base + (size_t)q0 * DH;
#pragma unroll
        for (int r = 0; r < 4; r++) {
            const int cc = tid + (r << 8);
            const int row = cc >> 3, ch = cc & 7;
            *(uint4*)(fsm + row * FROWB + ch * 16) =
                *(const uint4*)(qh + row * DH + ch * 8);
        }
    }
    __syncthreads();
    unsigned qf[4][4];
    {
        const unsigned qa = sb + (warp_m + (lane & 15)) * FROWB + ((lane >> 4) << 4);
#pragma unroll
        for (int t = 0; t < 4; t++)
            ldsm_x4(qf[t][0], qf[t][1], qf[t][2], qf[t][3], qa + t * 32);
    }
    __syncthreads();

    float o[8][4] = {};
    float lacc[4] = {};                    // row-sum accumulator (ones-MMA)
    float m0 = -1e30f, m1 = -1e30f;
    const int g  = lane >> 2;
    const int c4 = lane & 3;
    const int row0 = q0 + warp_m + g;
    const int row1 = row0 + 8;
    const unsigned bones[2] = {0x3C003C00u, 0x3C003C00u};

    const unsigned ka0 = sb + ((lane & 7) + ((lane >> 4) << 3)) * FROWB
                            + (((lane >> 3) & 1) << 4);
    const unsigned va0 = sb + FTILE
                            + ((lane & 7) + (((lane >> 3) & 1) << 3)) * FROWB
                            + ((lane >> 4) << 4);

    const int srow = tid >> 3, sch = tid & 7;
    const unsigned sso = srow * FROWB + sch * 16;
    const unsigned sgo = srow * DH + sch * 8;

    const int nkt = (q0 >> 6) + 2;

    // prologue: tile 0 -> stage 0
    {
        const __half* pk = g_Khi + base;
        const __half* pv = g_Vhi + base;
#pragma unroll
        for (int r = 0; r < 2; r++) {
            const unsigned so = sso + r * (32 * FROWB);
            const unsigned go = sgo + r * (32 * DH);
            CP_ASYNC16(sb + so, pk + go);
            CP_ASYNC16(sb + FTILE + so, pv + go);
        }
        CP_COMMIT();
    }

    for (int kt = 0; kt < nkt; kt++) {
        const int k0 = kt << 6;
        if (kt + 1 < nkt) {
            const size_t nb = base + (size_t)((kt + 1) << 6) * DH;
            const unsigned st = sb + ((kt + 1) & 1) * FSTAGE;
            const __half* pk = g_Khi + nb;
            const __half* pv = g_Vhi + nb;
#pragma unroll
            for (int r = 0; r < 2; r++) {
                const unsigned so = sso + r * (32 * FROWB);
                const unsigned go = sgo + r * (32 * DH);
                CP_ASYNC16(st + so, pk + go);
                CP_ASYNC16(st + FTILE + so, pv + go);
            }
            CP_COMMIT();
            CP_WAIT(1);
        } else {
            CP_WAIT(0);
        }
        __syncthreads();

        if (k0 <= q0 + warp_m + 15) {
            const unsigned stof = (kt & 1) * FSTAGE;
            const unsigned ka = ka0 + stof;
            const unsigned va = va0 + stof;

            float s[8][4];
#pragma unroll
            for (int j = 0; j < 8; j++)
#pragma unroll
                for (int x = 0; x < 4; x++) s[j][x] = 0.f;

#pragma unroll
            for (int t = 0; t < 4; t++) {
                unsigned kf[8][2];
#pragma unroll
                for (int jp = 0; jp < 4; jp++)
                    ldsm_x4(kf[2 * jp][0], kf[2 * jp][1],
                            kf[2 * jp + 1][0], kf[2 * jp + 1][1],
                            ka + jp * (16 * FROWB) + t * 32);
#pragma unroll
                for (int j = 0; j < 8; j++) mma16816(s[j], qf[t], kf[j]);
            }

            if (k0 + 63 > q0 + warp_m) {
#pragma unroll
                for (int j = 0; j < 8; j++) {
                    const int col = k0 + 8 * j + 2 * c4;
                    if (col     > row0) s[j][0] = -1e30f;
                    if (col + 1 > row0) s[j][1] = -1e30f;
                    if (col     > row1) s[j][2] = -1e30f;
                    if (col + 1 > row1) s[j][3] = -1e30f;
                }
            }

            float rx0 = -1e30f, rx1 = -1e30f;
#pragma unroll
            for (int j = 0; j < 8; j++) {
                rx0 = fmaxf(rx0, fmaxf(s[j][0], s[j][1]));
                rx1 = fmaxf(rx1, fmaxf(s[j][2], s[j][3]));
            }
            rx0 = fmaxf(rx0, __shfl_xor_sync(0xffffffffu, rx0, 1));
            rx0 = fmaxf(rx0, __shfl_xor_sync(0xffffffffu, rx0, 2));
            rx1 = fmaxf(rx1, __shfl_xor_sync(0xffffffffu, rx1, 1));
            rx1 = fmaxf(rx1, __shfl_xor_sync(0xffffffffu, rx1, 2));
            const float mn0 = fmaxf(m0, rx0), mn1 = fmaxf(m1, rx1);
            const float a0 = ex2f(m0 - mn0), a1 = ex2f(m1 - mn1);
            m0 = mn0;  m1 = mn1;

            // P in fp16 directly (ex2.approx.f16x2); masked -> -inf -> 0
            unsigned pf[8][2];
#pragma unroll
            for (int j = 0; j < 8; j++) {
                pf[j][0] = h2exp2u(cvt_h2(s[j][0] - mn0, s[j][1] - mn0));
                pf[j][1] = h2exp2u(cvt_h2(s[j][2] - mn1, s[j][3] - mn1));
            }

            // rescale running state
            lacc[0] *= a0; lacc[1] *= a0; lacc[2] *= a1; lacc[3] *= a1;
#pragma unroll
            for (int j = 0; j < 8; j++) {
                o[j][0] *= a0; o[j][1] *= a0; o[j][2] *= a1; o[j][3] *= a1;
            }

            // l += P @ ones  (4 MMAs, exactly consistent with PV's fp16 P)
#pragma unroll
            for (int t = 0; t < 4; t++) {
                unsigned afrag[4] = {pf[2 * t][0], pf[2 * t][1],
                                     pf[2 * t + 1][0], pf[2 * t + 1][1]};
                mma16816(lacc, afrag, bones);
            }

            // O += P V
#pragma unroll
            for (int t = 0; t < 4; t++) {
                unsigned afrag[4] = {pf[2 * t][0], pf[2 * t][1],
                                     pf[2 * t + 1][0], pf[2 * t + 1][1]};
#pragma unroll
                for (int j2 = 0; j2 < 4; j2++) {
                    unsigned v0, v1, v2, v3;
                    ldsm_x4_t(v0, v1, v2, v3, va + t * (16 * FROWB) + j2 * 32);
                    unsigned bA[2] = {v0, v1}, bB[2] = {v2, v3};
                    mma16816(o[2 * j2],     afrag, bA);
                    mma16816(o[2 * j2 + 1], afrag, bB);
                }
            }
        }
        __syncthreads();
    }

    // epilogue: normalize (l from ones-MMA), fp16 store to g_ahi [B,S,DM]
    const float i0 = 1.f / lacc[0], i1 = 1.f / lacc[2];
    const int tok0 = b * SEQ + q0 + warp_m + g;
    const int tok1 = tok0 + 8;
    const int colb = h * DH + 2 * c4;
#pragma unroll
    for (int j = 0; j < 8; j++) {
        *(unsigned*)(g_ahi + (size_t)tok0 * DM + colb + 8 * j) =
            cvt_h2(o[j][0] * i0, o[j][1] * i0);
        *(unsigned*)(g_ahi + (size_t)tok1 * DM + colb + 8 * j) =
            cvt_h2(o[j][2] * i1, o[j][3] * i1);
    }
}

// ---------------------------------------------------------------------------
extern "C" void kernel_launch(void* const* d_in, const int* in_sizes, int n_in,
                              void* d_out, int out_size)
{
    (void)in_sizes; (void)n_in; (void)out_size;
    const float* x    = (const float*)d_in[0];
    const float* Wqkv = (const float*)d_in[1];
    const float* bqkv = (const float*)d_in[2];
    const float* Wo   = (const float*)d_in[3];
    const float* bo   = (const float*)d_in[4];
    float* out = (float*)d_out;

    cudaFuncSetAttribute((const void*)tc_gemm_kernel<0, 24>,
                         cudaFuncAttributeMaxDynamicSharedMemorySize, GEMM_SMEM);
    cudaFuncSetAttribute((const void*)tc_gemm_kernel<1, 8>,
                         cudaFuncAttributeMaxDynamicSharedMemorySize, GEMM_SMEM);
    cudaFuncSetAttribute(flash_tc_kernel,
                         cudaFuncAttributeMaxDynamicSharedMemorySize, FLASH_SMEM);

    split_all_kernel<<<SPLIT_BLOCKS, 256>>>(x, Wqkv, Wo);

    tc_gemm_kernel<0, 24><<<PGRID, 256, GEMM_SMEM>>>(bqkv, nullptr, 1536);

    flash_tc_kernel<<<dim3(SEQ / 128, NH, BATCH), 256, FLASH_SMEM>>>();

    tc_gemm_kernel<1, 8><<<PGRID, 256, GEMM_SMEM>>>(bo, out, 512);
}